// round 11
// baseline (speedup 1.0000x reference)
#include <cuda_runtime.h>
#include <cuda_fp16.h>

#define N_USERS_C 200000
#define NTOT      400000
#define DIM       64
#define NNZ_E     12800000
#define NLAYERS   3
#define CHUNKS    (NTOT / 64)
#define NB2       ((NTOT + 4095) / 4096)     // 98

// ---- device-global scratch (allocation-free rule) ----
__device__ float   g_ego[2][(size_t)NTOT * DIM];     // fp32 ego (ping-pong)
__device__ __half2 g_egoh[2][(size_t)NTOT * 32];     // fp16 shadow (gather source)
__device__ int   g_cnt[NTOT];
__device__ int   g_scan[NTOT];
__device__ int   g_rp[NTOT + 1];
__device__ int   g_cur[NTOT];
__device__ int   g_bsum[NB2];
__device__ int   g_boff[NB2];
__device__ int2  g_csv[NNZ_E];               // (col, float-bits of val)

// L2 evict-last policy + hinted 64-bit gather (keeps the hot fp16 ego pinned)
__device__ __forceinline__ unsigned long long mk_evict_last() {
    unsigned long long pol;
    asm("createpolicy.fractional.L2::evict_last.b64 %0, 1.0;" : "=l"(pol));
    return pol;
}
__device__ __forceinline__ uint2 ldg_h(const uint2* p, unsigned long long pol) {
    uint2 r;
    asm volatile("ld.global.nc.L2::cache_hint.v2.u32 {%0,%1}, [%2], %3;"
                 : "=r"(r.x), "=r"(r.y) : "l"(p), "l"(pol));
    return r;
}

// ---------------------------------------------------------------------------
// Init: ego0 (fp32 + fp16 shadow) and layer-0 columns of out. Thread per pair.
// ---------------------------------------------------------------------------
__global__ void init_kernel(const float* __restrict__ ue,
                            const float* __restrict__ ie,
                            float* __restrict__ out) {
    int idx = blockIdx.x * blockDim.x + threadIdx.x;  // pair index
    if (idx >= NTOT * 32) return;
    int node = idx >> 5;
    int dp = idx & 31;
    const float2* src = (node < N_USERS_C)
        ? (const float2*)ue + idx
        : (const float2*)ie + (idx - N_USERS_C * 32);
    float2 v = __ldg(src);
    *(float2*)&g_ego[0][(size_t)node * 64 + dp * 2] = v;
    g_egoh[0][(size_t)node * 32 + dp] = __floats2half2_rn(v.x, v.y);
    *(float2*)&out[(size_t)node * 256 + dp * 2] = v;
}

__global__ void zero_cnt_kernel() {
    int i = blockIdx.x * blockDim.x + threadIdx.x;
    if (i < NTOT) g_cnt[i] = 0;
}

__global__ void hist_kernel(const int* __restrict__ rows) {
    int e = blockIdx.x * blockDim.x + threadIdx.x;
    if (e < NNZ_E) atomicAdd(&g_cnt[__ldg(rows + e)], 1);
}

// Per-block exclusive scan of 4096 counts (1024 thr x 4); block total to g_bsum.
__global__ void scan_local_kernel() {
    __shared__ int wsum[32];
    int b = blockIdx.x, t = threadIdx.x;
    int base = b * 4096 + t * 4;
    int v0 = 0, v1 = 0, v2 = 0, v3 = 0;
    if (base + 0 < NTOT) v0 = g_cnt[base + 0];
    if (base + 1 < NTOT) v1 = g_cnt[base + 1];
    if (base + 2 < NTOT) v2 = g_cnt[base + 2];
    if (base + 3 < NTOT) v3 = g_cnt[base + 3];
    int tsum = v0 + v1 + v2 + v3;
    int lane = t & 31, w = t >> 5;
    int x = tsum;
#pragma unroll
    for (int d = 1; d < 32; d <<= 1) {
        int y = __shfl_up_sync(0xffffffffu, x, d);
        if (lane >= d) x += y;
    }
    if (lane == 31) wsum[w] = x;
    __syncthreads();
    if (t < 32) {
        int y = wsum[t];
#pragma unroll
        for (int d = 1; d < 32; d <<= 1) {
            int z = __shfl_up_sync(0xffffffffu, y, d);
            if (t >= d) y += z;
        }
        wsum[t] = y;
    }
    __syncthreads();
    int woff = (w == 0) ? 0 : wsum[w - 1];
    int ex = woff + x - tsum;
    if (base + 0 < NTOT) g_scan[base + 0] = ex;
    ex += v0;
    if (base + 1 < NTOT) g_scan[base + 1] = ex;
    ex += v1;
    if (base + 2 < NTOT) g_scan[base + 2] = ex;
    ex += v2;
    if (base + 3 < NTOT) g_scan[base + 3] = ex;
    if (t == 0) g_bsum[b] = wsum[31];
}

// Exclusive scan of the NB2 (=98) block sums (single block of 128).
__global__ void scan_block_kernel() {
    __shared__ int wsum[4];
    int t = threadIdx.x;
    int v = (t < NB2) ? g_bsum[t] : 0;
    int lane = t & 31, w = t >> 5;
    int x = v;
#pragma unroll
    for (int d = 1; d < 32; d <<= 1) {
        int y = __shfl_up_sync(0xffffffffu, x, d);
        if (lane >= d) x += y;
    }
    if (lane == 31) wsum[w] = x;
    __syncthreads();
    if (t < 4) {
        int y = wsum[t];
#pragma unroll
        for (int d = 1; d < 4; d <<= 1) {
            int z = __shfl_up_sync(0xFu, y, d, 4);
            if (t >= d) y += z;
        }
        wsum[t] = y;
    }
    __syncthreads();
    int woff = (w == 0) ? 0 : wsum[w - 1];
    if (t < NB2) g_boff[t] = woff + x - v;
}

__global__ void scan_finish_kernel() {
    int i = blockIdx.x * blockDim.x + threadIdx.x;
    if (i < NTOT) {
        int r = g_scan[i] + g_boff[i >> 12];
        g_rp[i] = r;
        g_cur[i] = r;
    }
    if (i == 0) g_rp[NTOT] = NNZ_E;
}

__global__ void scatter_kernel(const int* __restrict__ rows,
                               const int* __restrict__ cols,
                               const float* __restrict__ vals) {
    int e = blockIdx.x * blockDim.x + threadIdx.x;
    if (e >= NNZ_E) return;
    int r = __ldg(rows + e);
    int c = __ldg(cols + e);
    float v = __ldg(vals + e);
    int pos = atomicAdd(&g_cur[r], 1);
    g_csv[pos] = make_int2(c, __float_as_int(v));
}

// ---------------------------------------------------------------------------
// Fused layer: full CSR SpMM (fp16 gather / fp32 accumulate) -> smem tiles ->
// GC/Bi GEMM + lrelu + row-L2-normalize -> out + fp32 ego_next + fp16 shadow.
// Block = 256 = 16 half-warps; chunk = 64 rows; half-warp h owns 4 rows,
// lane j owns dims [4j, 4j+4).
// ---------------------------------------------------------------------------
__global__ void __launch_bounds__(256)
fused_layer_kernel(const float* __restrict__ gw,
                   const float* __restrict__ gb,
                   const float* __restrict__ bw,
                   const float* __restrict__ bb,
                   float* __restrict__ out,
                   int col_off, int pp) {
    extern __shared__ float sh[];
    float* s_wgc  = sh;                 // 4096: wT[k*64+d]
    float* s_wbi  = sh + 4096;          // 4096
    float* s_side = sh + 8192;          // 64*68
    float* s_prod = sh + 8192 + 4352;   // 64*68 (reused as e-buffer)

    const float*  ego = g_ego[pp];
    float*   ego_next = g_ego[pp ^ 1];
    const float4* x4  = (const float4*)ego;
    const uint2*  xh  = (const uint2*)g_egoh[pp];      // 16 uint2 per row
    __half2* egoh_next = g_egoh[pp ^ 1];

    int t = threadIdx.x;
    int j = t & 15;
    int h = t >> 4;
    unsigned hmask = 0xFFFFu << (t & 16);
    unsigned long long pol = mk_evict_last();

    for (int idx = t; idx < 4096; idx += 256) {
        int d = idx & 63, k = idx >> 6;
        s_wgc[k * 64 + d] = gw[d * 64 + k];
        s_wbi[k * 64 + d] = bw[d * 64 + k];
    }

    const int d0 = (t & 15) * 4;
    const int n0 = (t >> 4) * 4;
    float bg[4], bbv[4];
#pragma unroll
    for (int q = 0; q < 4; q++) {
        bg[q]  = __ldg(gb + d0 + q);
        bbv[q] = __ldg(bb + d0 + q);
    }

    for (int c = blockIdx.x; c < CHUNKS; c += gridDim.x) {
        __syncthreads();
        int base = c * 64;

        // ---- Phase 1: full-row SpMM, fp16 gather (1 line/row) ----
#pragma unroll
        for (int i = 0; i < 4; i++) {
            int r = base + h * 4 + i;
            int s = __ldg(g_rp + r), e = __ldg(g_rp + r + 1);
            float4 acc = make_float4(0.f, 0.f, 0.f, 0.f);
            for (int p = s; p < e; p += 16) {
                int idx = p + j;
                int cj = -1; float vj = 0.f;
                if (idx < e) {
                    int2 cv = __ldcs(g_csv + idx);
                    cj = cv.x; vj = __int_as_float(cv.y);
                }
#pragma unroll
                for (int q = 0; q < 16; q++) {
                    int cc   = __shfl_sync(hmask, cj, q, 16);
                    float vv = __shfl_sync(hmask, vj, q, 16);
                    if (cc >= 0) {
                        uint2 u = ldg_h(xh + (size_t)cc * 16 + j, pol);
                        float2 fa = __half22float2(*(__half2*)&u.x);
                        float2 fb = __half22float2(*(__half2*)&u.y);
                        acc.x += vv * fa.x;
                        acc.y += vv * fa.y;
                        acc.z += vv * fb.x;
                        acc.w += vv * fb.y;
                    }
                }
            }
            float4 ev = __ldg(x4 + (size_t)r * 16 + j);   // fp32 ego for Bi branch
            int node = h * 4 + i;
            *(float4*)&s_side[node * 68 + j * 4] = acc;
            *(float4*)&s_prod[node * 68 + j * 4] =
                make_float4(acc.x * ev.x, acc.y * ev.y, acc.z * ev.z, acc.w * ev.w);
        }
        __syncthreads();

        // ---- Phase 2: dense GC/Bi GEMM (4 nodes x 4 dims per thread) ----
        float accg[4][4], accb[4][4];
#pragma unroll
        for (int i = 0; i < 4; i++)
#pragma unroll
            for (int q = 0; q < 4; q++) {
                accg[i][q] = bg[q];
                accb[i][q] = bbv[q];
            }

#pragma unroll 8
        for (int k = 0; k < 64; k++) {
            float4 wg = *(const float4*)&s_wgc[k * 64 + d0];
            float4 wb = *(const float4*)&s_wbi[k * 64 + d0];
            float sv[4], pv[4];
#pragma unroll
            for (int i = 0; i < 4; i++) {
                sv[i] = s_side[(n0 + i) * 68 + k];
                pv[i] = s_prod[(n0 + i) * 68 + k];
            }
#pragma unroll
            for (int i = 0; i < 4; i++) {
                accg[i][0] += sv[i] * wg.x;
                accg[i][1] += sv[i] * wg.y;
                accg[i][2] += sv[i] * wg.z;
                accg[i][3] += sv[i] * wg.w;
                accb[i][0] += pv[i] * wb.x;
                accb[i][1] += pv[i] * wb.y;
                accb[i][2] += pv[i] * wb.z;
                accb[i][3] += pv[i] * wb.w;
            }
        }
        __syncthreads();

        // e = lrelu(gc) + lrelu(bi) into smem (reuse s_prod)
#pragma unroll
        for (int i = 0; i < 4; i++)
#pragma unroll
            for (int q = 0; q < 4; q++) {
                float a = accg[i][q], b = accb[i][q];
                float e = fmaxf(a, 0.01f * a) + fmaxf(b, 0.01f * b);
                s_prod[(n0 + i) * 68 + d0 + q] = e;
            }
        __syncthreads();

        // Row norms + global writes: thread -> (node = t/4, quarter = t%4)
        int node = t >> 2, qq = t & 3;
        float ss = 0.f;
#pragma unroll
        for (int m = 0; m < 16; m++) {
            float v = s_prod[node * 68 + qq * 16 + m];
            ss += v * v;
        }
        ss += __shfl_xor_sync(0xffffffffu, ss, 1);
        ss += __shfl_xor_sync(0xffffffffu, ss, 2);
        float inv = 1.f / fmaxf(sqrtf(ss), 1e-12f);

        size_t gnode = (size_t)(base + node);
        unsigned hbuf[8];
#pragma unroll
        for (int m = 0; m < 16; m += 4) {
            float4 v = *(const float4*)&s_prod[node * 68 + qq * 16 + m];
            *(float4*)&ego_next[gnode * 64 + qq * 16 + m] = v;
            __half2 h0 = __floats2half2_rn(v.x, v.y);
            __half2 h1 = __floats2half2_rn(v.z, v.w);
            hbuf[m / 2]     = *(unsigned*)&h0;
            hbuf[m / 2 + 1] = *(unsigned*)&h1;
            float4 vn = make_float4(v.x * inv, v.y * inv, v.z * inv, v.w * inv);
            __stcs((float4*)&out[gnode * 256 + col_off + qq * 16 + m], vn);
        }
        // fp16 shadow for next layer's gathers (2x 16B stores)
        uint4* hp = (uint4*)&egoh_next[gnode * 32 + qq * 8];
        hp[0] = make_uint4(hbuf[0], hbuf[1], hbuf[2], hbuf[3]);
        hp[1] = make_uint4(hbuf[4], hbuf[5], hbuf[6], hbuf[7]);
    }
}

// ---------------------------------------------------------------------------
extern "C" void kernel_launch(void* const* d_in, const int* in_sizes, int n_in,
                              void* d_out, int out_size) {
    const int*   rows = (const int*)d_in[0];
    const int*   cols = (const int*)d_in[1];
    const float* vals = (const float*)d_in[2];
    const float* ue   = (const float*)d_in[3];
    const float* ie   = (const float*)d_in[4];
    const float* gw   = (const float*)d_in[5];
    const float* gb   = (const float*)d_in[6];
    const float* bw   = (const float*)d_in[7];
    const float* bb   = (const float*)d_in[8];
    float* out = (float*)d_out;

    const int smem_bytes = (4096 * 2 + 4352 * 2) * 4;  // 67584 B
    cudaFuncSetAttribute(fused_layer_kernel,
                         cudaFuncAttributeMaxDynamicSharedMemorySize, smem_bytes);

    init_kernel<<<(NTOT * 32 + 255) / 256, 256>>>(ue, ie, out);

    // ---- CSR build (once; reused by all 3 layers) ----
    zero_cnt_kernel<<<(NTOT + 255) / 256, 256>>>();
    hist_kernel<<<(NNZ_E + 255) / 256, 256>>>(rows);
    scan_local_kernel<<<NB2, 1024>>>();
    scan_block_kernel<<<1, 128>>>();
    scan_finish_kernel<<<(NTOT + 255) / 256, 256>>>();
    scatter_kernel<<<(NNZ_E + 255) / 256, 256>>>(rows, cols, vals);

    // ---- 3 fused layers (single kernel each) ----
    for (int i = 0; i < NLAYERS; i++) {
        int pp = i & 1;
        fused_layer_kernel<<<CHUNKS, 256, smem_bytes>>>(
            gw + i * 4096, gb + i * 64, bw + i * 4096, bb + i * 64,
            out, (i + 1) * 64, pp);
    }
}

// round 12
// speedup vs baseline: 1.0645x; 1.0645x over previous
#include <cuda_runtime.h>

#define N_USERS_C 200000
#define NTOT      400000
#define DIM       64
#define NNZ_E     12800000
#define NLAYERS   3
#define CHUNKS    (NTOT / 64)

#define NTILES    2
#define TSPLIT    200000
#define NSEG      (NTOT * NTILES)            // 800,000
#define NB2       ((NSEG + 4095) / 4096)     // 196

typedef unsigned long long ull;

// ---- device-global scratch (allocation-free rule) ----
__device__ float g_ego[2][(size_t)NTOT * DIM];
__device__ float g_side[(size_t)NTOT * DIM];
__device__ int   g_cnt[NSEG];
__device__ int   g_scan[NSEG];
__device__ int   g_rp2[NSEG + 1];
__device__ int   g_cur[NSEG];
__device__ int   g_bsum[NB2];
__device__ int   g_boff[NB2];
__device__ int2  g_csv[NNZ_E];               // (col, float-bits of val)

// L2 evict-last policy + hinted 128-bit gather (keeps the hot ego slice pinned)
__device__ __forceinline__ ull mk_evict_last() {
    ull pol;
    asm("createpolicy.fractional.L2::evict_last.b64 %0, 1.0;" : "=l"(pol));
    return pol;
}
__device__ __forceinline__ float4 ldg_el(const float4* p, ull pol) {
    float4 r;
    asm volatile("ld.global.nc.L2::cache_hint.v4.f32 {%0,%1,%2,%3}, [%4], %5;"
                 : "=f"(r.x), "=f"(r.y), "=f"(r.z), "=f"(r.w)
                 : "l"(p), "l"(pol));
    return r;
}

// Packed f32x2 helpers (FFMA2 — only reachable via PTX on sm_103a)
__device__ __forceinline__ ull pack2(float lo, float hi) {
    ull r; asm("mov.b64 %0, {%1,%2};" : "=l"(r) : "f"(lo), "f"(hi)); return r;
}
__device__ __forceinline__ ull fma2(ull a, ull b, ull c) {
    ull d; asm("fma.rn.f32x2 %0, %1, %2, %3;" : "=l"(d) : "l"(a), "l"(b), "l"(c));
    return d;
}
__device__ __forceinline__ float2 unpack2(ull v) {
    float2 r; asm("mov.b64 {%0,%1}, %2;" : "=f"(r.x), "=f"(r.y) : "l"(v)); return r;
}

// ---------------------------------------------------------------------------
__global__ void init_kernel(const float* __restrict__ ue,
                            const float* __restrict__ ie,
                            float* __restrict__ out) {
    int idx = blockIdx.x * blockDim.x + threadIdx.x;
    if (idx >= NTOT * DIM) return;
    int node = idx >> 6;
    int d = idx & 63;
    float v = (node < N_USERS_C) ? ue[idx] : ie[idx - N_USERS_C * DIM];
    g_ego[0][idx] = v;
    out[(size_t)node * 256 + d] = v;
}

__global__ void zero_cnt_kernel() {
    int i = blockIdx.x * blockDim.x + threadIdx.x;
    if (i < NSEG) g_cnt[i] = 0;
}

__global__ void hist_kernel(const int* __restrict__ rows,
                            const int* __restrict__ cols) {
    int e = blockIdx.x * blockDim.x + threadIdx.x;
    if (e >= NNZ_E) return;
    int r = __ldg(rows + e);
    int c = __ldg(cols + e);
    int t = (c >= TSPLIT);
    atomicAdd(&g_cnt[r * NTILES + t], 1);
}

// Per-block exclusive scan of 4096 counts (1024 thr x 4); block total to g_bsum.
__global__ void scan_local_kernel() {
    __shared__ int wsum[32];
    int b = blockIdx.x, t = threadIdx.x;
    int base = b * 4096 + t * 4;
    int v0 = 0, v1 = 0, v2 = 0, v3 = 0;
    if (base + 0 < NSEG) v0 = g_cnt[base + 0];
    if (base + 1 < NSEG) v1 = g_cnt[base + 1];
    if (base + 2 < NSEG) v2 = g_cnt[base + 2];
    if (base + 3 < NSEG) v3 = g_cnt[base + 3];
    int tsum = v0 + v1 + v2 + v3;
    int lane = t & 31, w = t >> 5;
    int x = tsum;
#pragma unroll
    for (int d = 1; d < 32; d <<= 1) {
        int y = __shfl_up_sync(0xffffffffu, x, d);
        if (lane >= d) x += y;
    }
    if (lane == 31) wsum[w] = x;
    __syncthreads();
    if (t < 32) {
        int y = wsum[t];
#pragma unroll
        for (int d = 1; d < 32; d <<= 1) {
            int z = __shfl_up_sync(0xffffffffu, y, d);
            if (t >= d) y += z;
        }
        wsum[t] = y;
    }
    __syncthreads();
    int woff = (w == 0) ? 0 : wsum[w - 1];
    int ex = woff + x - tsum;
    if (base + 0 < NSEG) g_scan[base + 0] = ex;
    ex += v0;
    if (base + 1 < NSEG) g_scan[base + 1] = ex;
    ex += v1;
    if (base + 2 < NSEG) g_scan[base + 2] = ex;
    ex += v2;
    if (base + 3 < NSEG) g_scan[base + 3] = ex;
    if (t == 0) g_bsum[b] = wsum[31];
}

// Exclusive scan of the NB2 block sums (single block of 256).
__global__ void scan_block_kernel() {
    __shared__ int wsum[8];
    int t = threadIdx.x;
    int v = (t < NB2) ? g_bsum[t] : 0;
    int lane = t & 31, w = t >> 5;
    int x = v;
#pragma unroll
    for (int d = 1; d < 32; d <<= 1) {
        int y = __shfl_up_sync(0xffffffffu, x, d);
        if (lane >= d) x += y;
    }
    if (lane == 31) wsum[w] = x;
    __syncthreads();
    if (t < 8) {
        int y = wsum[t];
#pragma unroll
        for (int d = 1; d < 8; d <<= 1) {
            int z = __shfl_up_sync(0xffu, y, d, 8);
            if (t >= d) y += z;
        }
        wsum[t] = y;
    }
    __syncthreads();
    int woff = (w == 0) ? 0 : wsum[w - 1];
    if (t < NB2) g_boff[t] = woff + x - v;
}

__global__ void scan_finish_kernel() {
    int i = blockIdx.x * blockDim.x + threadIdx.x;
    if (i < NSEG) {
        int r = g_scan[i] + g_boff[i >> 12];
        g_rp2[i] = r;
        g_cur[i] = r;
    }
    if (i == 0) g_rp2[NSEG] = NNZ_E;
}

__global__ void scatter_kernel(const int* __restrict__ rows,
                               const int* __restrict__ cols,
                               const float* __restrict__ vals) {
    int e = blockIdx.x * blockDim.x + threadIdx.x;
    if (e >= NNZ_E) return;
    int r = __ldg(rows + e);
    int c = __ldg(cols + e);
    float v = __ldg(vals + e);
    int t = (c >= TSPLIT);
    int pos = atomicAdd(&g_cur[r * NTILES + t], 1);
    g_csv[pos] = make_int2(c, __float_as_int(v));
}

// ---------------------------------------------------------------------------
// SpMM pass over column tile 0 (cols < TSPLIT): half-warp per row, exclusive
// ownership, write-only into g_side (streaming stores).
// ---------------------------------------------------------------------------
__global__ void __launch_bounds__(256)
spmm_pass_kernel(int pp) {
    int gtid = blockIdx.x * blockDim.x + threadIdx.x;
    int r = gtid >> 4;
    if (r >= NTOT) return;
    int j = threadIdx.x & 15;
    unsigned hmask = 0xFFFFu << (threadIdx.x & 16);
    ull pol = mk_evict_last();

    const float4* x4 = (const float4*)g_ego[pp];
    float4* side4 = (float4*)g_side;

    int s = __ldg(g_rp2 + r * NTILES);
    int e = __ldg(g_rp2 + r * NTILES + 1);

    float4 acc = make_float4(0.f, 0.f, 0.f, 0.f);
    for (int p = s; p < e; p += 16) {
        int idx = p + j;
        int cj = -1; float vj = 0.f;
        if (idx < e) {
            int2 cv = __ldcs(g_csv + idx);
            cj = cv.x; vj = __int_as_float(cv.y);
        }
#pragma unroll
        for (int q = 0; q < 16; q++) {
            int cc   = __shfl_sync(hmask, cj, q, 16);
            float vv = __shfl_sync(hmask, vj, q, 16);
            if (cc >= 0) {
                float4 g4 = ldg_el(x4 + (size_t)cc * 16 + j, pol);
                acc.x += vv * g4.x;
                acc.y += vv * g4.y;
                acc.z += vv * g4.z;
                acc.w += vv * g4.w;
            }
        }
    }
    __stcs(side4 + (size_t)r * 16 + j, acc);
}

// ---------------------------------------------------------------------------
// Fused: tile-1 SpMM (seeded with g_side partial) -> smem tiles ->
// GC/Bi GEMM (packed f32x2 FFMA2) + lrelu + row-L2-normalize -> out + ego_next.
// ---------------------------------------------------------------------------
__global__ void __launch_bounds__(256)
fused_layer_kernel(const float* __restrict__ gw,
                   const float* __restrict__ gb,
                   const float* __restrict__ bw,
                   const float* __restrict__ bb,
                   float* __restrict__ out,
                   int col_off, int pp) {
    extern __shared__ float sh[];
    float* s_wgc  = sh;                 // 4096: wT[k*64+d]
    float* s_wbi  = sh + 4096;          // 4096
    float* s_side = sh + 8192;          // 64*68
    float* s_prod = sh + 8192 + 4352;   // 64*68 (reused as e-buffer)

    const float*  ego = g_ego[pp];
    float*   ego_next = g_ego[pp ^ 1];
    const float4* x4  = (const float4*)ego;
    const float4* side4 = (const float4*)g_side;

    int t = threadIdx.x;
    int j = t & 15;
    int h = t >> 4;
    unsigned hmask = 0xFFFFu << (t & 16);
    ull pol = mk_evict_last();

    for (int idx = t; idx < 4096; idx += 256) {
        int d = idx & 63, k = idx >> 6;
        s_wgc[k * 64 + d] = gw[d * 64 + k];
        s_wbi[k * 64 + d] = bw[d * 64 + k];
    }

    const int d0 = (t & 15) * 4;
    const int n0 = (t >> 4) * 4;
    ull bg2[2], bb2[2];
#pragma unroll
    for (int p = 0; p < 2; p++) {
        bg2[p] = pack2(__ldg(gb + d0 + 2 * p), __ldg(gb + d0 + 2 * p + 1));
        bb2[p] = pack2(__ldg(bb + d0 + 2 * p), __ldg(bb + d0 + 2 * p + 1));
    }

    for (int c = blockIdx.x; c < CHUNKS; c += gridDim.x) {
        __syncthreads();
        int base = c * 64;

        // ---- Phase 1: tile-1 SpMM seeded with side partial ----
#pragma unroll
        for (int i = 0; i < 4; i++) {
            int r = base + h * 4 + i;
            int s = __ldg(g_rp2 + r * NTILES + 1);
            int e = __ldg(g_rp2 + r * NTILES + 2);
            float4 acc = __ldcs(side4 + (size_t)r * 16 + j);
            for (int p = s; p < e; p += 16) {
                int idx = p + j;
                int cj = -1; float vj = 0.f;
                if (idx < e) {
                    int2 cv = __ldcs(g_csv + idx);
                    cj = cv.x; vj = __int_as_float(cv.y);
                }
#pragma unroll
                for (int q = 0; q < 16; q++) {
                    int cc   = __shfl_sync(hmask, cj, q, 16);
                    float vv = __shfl_sync(hmask, vj, q, 16);
                    if (cc >= 0) {
                        float4 g4 = ldg_el(x4 + (size_t)cc * 16 + j, pol);
                        acc.x += vv * g4.x;
                        acc.y += vv * g4.y;
                        acc.z += vv * g4.z;
                        acc.w += vv * g4.w;
                    }
                }
            }
            float4 ev = __ldg(x4 + (size_t)r * 16 + j);
            int node = h * 4 + i;
            *(float4*)&s_side[node * 68 + j * 4] = acc;
            *(float4*)&s_prod[node * 68 + j * 4] =
                make_float4(acc.x * ev.x, acc.y * ev.y, acc.z * ev.z, acc.w * ev.w);
        }
        __syncthreads();

        // ---- Phase 2: dense GC/Bi GEMM via packed f32x2 (FFMA2) ----
        ull accg2[4][2], accb2[4][2];
#pragma unroll
        for (int i = 0; i < 4; i++)
#pragma unroll
            for (int p = 0; p < 2; p++) {
                accg2[i][p] = bg2[p];
                accb2[i][p] = bb2[p];
            }

#pragma unroll 8
        for (int k = 0; k < 64; k++) {
            const ull* wgp = (const ull*)&s_wgc[k * 64 + d0];
            const ull* wbp = (const ull*)&s_wbi[k * 64 + d0];
            ull wg0 = wgp[0], wg1 = wgp[1];
            ull wb0 = wbp[0], wb1 = wbp[1];
#pragma unroll
            for (int i = 0; i < 4; i++) {
                float sv = s_side[(n0 + i) * 68 + k];
                float pv = s_prod[(n0 + i) * 68 + k];
                ull sv2 = pack2(sv, sv);
                ull pv2 = pack2(pv, pv);
                accg2[i][0] = fma2(sv2, wg0, accg2[i][0]);
                accg2[i][1] = fma2(sv2, wg1, accg2[i][1]);
                accb2[i][0] = fma2(pv2, wb0, accb2[i][0]);
                accb2[i][1] = fma2(pv2, wb1, accb2[i][1]);
            }
        }
        __syncthreads();

        // e = lrelu(gc) + lrelu(bi) into smem (reuse s_prod)
#pragma unroll
        for (int i = 0; i < 4; i++)
#pragma unroll
            for (int p = 0; p < 2; p++) {
                float2 a = unpack2(accg2[i][p]);
                float2 b = unpack2(accb2[i][p]);
                float e0 = fmaxf(a.x, 0.01f * a.x) + fmaxf(b.x, 0.01f * b.x);
                float e1 = fmaxf(a.y, 0.01f * a.y) + fmaxf(b.y, 0.01f * b.y);
                s_prod[(n0 + i) * 68 + d0 + 2 * p]     = e0;
                s_prod[(n0 + i) * 68 + d0 + 2 * p + 1] = e1;
            }
        __syncthreads();

        // Row norms + global writes: thread -> (node = t/4, quarter = t%4)
        int node = t >> 2, qq = t & 3;
        float ss = 0.f;
#pragma unroll
        for (int m = 0; m < 16; m++) {
            float v = s_prod[node * 68 + qq * 16 + m];
            ss += v * v;
        }
        ss += __shfl_xor_sync(0xffffffffu, ss, 1);
        ss += __shfl_xor_sync(0xffffffffu, ss, 2);
        float inv = 1.f / fmaxf(sqrtf(ss), 1e-12f);

        size_t gnode = (size_t)(base + node);
#pragma unroll
        for (int m = 0; m < 16; m += 4) {
            float4 v = *(const float4*)&s_prod[node * 68 + qq * 16 + m];
            *(float4*)&ego_next[gnode * 64 + qq * 16 + m] = v;
            float4 vn = make_float4(v.x * inv, v.y * inv, v.z * inv, v.w * inv);
            __stcs((float4*)&out[gnode * 256 + col_off + qq * 16 + m], vn);
        }
    }
}

// ---------------------------------------------------------------------------
extern "C" void kernel_launch(void* const* d_in, const int* in_sizes, int n_in,
                              void* d_out, int out_size) {
    const int*   rows = (const int*)d_in[0];
    const int*   cols = (const int*)d_in[1];
    const float* vals = (const float*)d_in[2];
    const float* ue   = (const float*)d_in[3];
    const float* ie   = (const float*)d_in[4];
    const float* gw   = (const float*)d_in[5];
    const float* gb   = (const float*)d_in[6];
    const float* bw   = (const float*)d_in[7];
    const float* bb   = (const float*)d_in[8];
    float* out = (float*)d_out;

    const int smem_bytes = (4096 * 2 + 4352 * 2) * 4;  // 67584 B
    cudaFuncSetAttribute(fused_layer_kernel,
                         cudaFuncAttributeMaxDynamicSharedMemorySize, smem_bytes);

    init_kernel<<<(NTOT * DIM + 255) / 256, 256>>>(ue, ie, out);

    // ---- (row, col-tile)-sorted edge list build (once; reused by all layers) ----
    zero_cnt_kernel<<<(NSEG + 255) / 256, 256>>>();
    hist_kernel<<<(NNZ_E + 255) / 256, 256>>>(rows, cols);
    scan_local_kernel<<<NB2, 1024>>>();
    scan_block_kernel<<<1, 256>>>();
    scan_finish_kernel<<<(NSEG + 255) / 256, 256>>>();
    scatter_kernel<<<(NNZ_E + 255) / 256, 256>>>(rows, cols, vals);

    // ---- 3 layers: tile-0 pass + fused(tile-1 + dense) ----
    const int pass_blocks = (NTOT * 16 + 255) / 256;  // one half-warp per row
    for (int i = 0; i < NLAYERS; i++) {
        int pp = i & 1;
        spmm_pass_kernel<<<pass_blocks, 256>>>(pp);
        fused_layer_kernel<<<CHUNKS, 256, smem_bytes>>>(
            gw + i * 4096, gb + i * 64, bw + i * 4096, bb + i * 64,
            out, (i + 1) * 64, pp);
    }
}

// round 13
// speedup vs baseline: 1.0747x; 1.0095x over previous
#include <cuda_runtime.h>

#define N_USERS_C 200000
#define NTOT      400000
#define DIM       64
#define NNZ_E     12800000
#define NLAYERS   3
#define CHUNKS    (NTOT / 64)

#define NTILES    2
#define TSPLIT    200000
#define NSEG      (NTOT * NTILES)            // 800,000
#define NB2       ((NSEG + 4095) / 4096)     // 196

typedef unsigned long long ull;

// ---- device-global scratch (allocation-free rule) ----
__device__ float g_ego[2][(size_t)NTOT * DIM];
__device__ float g_side[(size_t)NTOT * DIM];
__device__ int   g_cnt[NSEG];
__device__ int   g_scan[NSEG];
__device__ int   g_rp2[NSEG + 1];
__device__ int   g_cur[NSEG];
__device__ int   g_bsum[NB2];
__device__ int   g_boff[NB2];
__device__ int2  g_csv[NNZ_E];               // (col, float-bits of val)

// L2 evict-last policy + hinted 128-bit gather (keeps the hot ego slice pinned)
__device__ __forceinline__ ull mk_evict_last() {
    ull pol;
    asm("createpolicy.fractional.L2::evict_last.b64 %0, 1.0;" : "=l"(pol));
    return pol;
}
__device__ __forceinline__ float4 ldg_el(const float4* p, ull pol) {
    float4 r;
    asm volatile("ld.global.nc.L2::cache_hint.v4.f32 {%0,%1,%2,%3}, [%4], %5;"
                 : "=f"(r.x), "=f"(r.y), "=f"(r.z), "=f"(r.w)
                 : "l"(p), "l"(pol));
    return r;
}

// Packed f32x2 helpers (FFMA2 — only reachable via PTX on sm_103a)
__device__ __forceinline__ ull pack2(float lo, float hi) {
    ull r; asm("mov.b64 %0, {%1,%2};" : "=l"(r) : "f"(lo), "f"(hi)); return r;
}
__device__ __forceinline__ ull fma2(ull a, ull b, ull c) {
    ull d; asm("fma.rn.f32x2 %0, %1, %2, %3;" : "=l"(d) : "l"(a), "l"(b), "l"(c));
    return d;
}
__device__ __forceinline__ float2 unpack2(ull v) {
    float2 r; asm("mov.b64 {%0,%1}, %2;" : "=f"(r.x), "=f"(r.y) : "l"(v)); return r;
}

// ---------------------------------------------------------------------------
__global__ void init_kernel(const float* __restrict__ ue,
                            const float* __restrict__ ie,
                            float* __restrict__ out) {
    int idx = blockIdx.x * blockDim.x + threadIdx.x;
    if (idx >= NTOT * DIM) return;
    int node = idx >> 6;
    int d = idx & 63;
    float v = (node < N_USERS_C) ? ue[idx] : ie[idx - N_USERS_C * DIM];
    g_ego[0][idx] = v;
    out[(size_t)node * 256 + d] = v;
}

__global__ void zero_cnt_kernel() {
    int i = blockIdx.x * blockDim.x + threadIdx.x;
    if (i < NSEG) g_cnt[i] = 0;
}

__global__ void hist_kernel(const int* __restrict__ rows,
                            const int* __restrict__ cols) {
    int e = blockIdx.x * blockDim.x + threadIdx.x;
    if (e >= NNZ_E) return;
    int r = __ldg(rows + e);
    int c = __ldg(cols + e);
    int t = (c >= TSPLIT);
    atomicAdd(&g_cnt[r * NTILES + t], 1);
}

// Per-block exclusive scan of 4096 counts (1024 thr x 4); block total to g_bsum.
__global__ void scan_local_kernel() {
    __shared__ int wsum[32];
    int b = blockIdx.x, t = threadIdx.x;
    int base = b * 4096 + t * 4;
    int v0 = 0, v1 = 0, v2 = 0, v3 = 0;
    if (base + 0 < NSEG) v0 = g_cnt[base + 0];
    if (base + 1 < NSEG) v1 = g_cnt[base + 1];
    if (base + 2 < NSEG) v2 = g_cnt[base + 2];
    if (base + 3 < NSEG) v3 = g_cnt[base + 3];
    int tsum = v0 + v1 + v2 + v3;
    int lane = t & 31, w = t >> 5;
    int x = tsum;
#pragma unroll
    for (int d = 1; d < 32; d <<= 1) {
        int y = __shfl_up_sync(0xffffffffu, x, d);
        if (lane >= d) x += y;
    }
    if (lane == 31) wsum[w] = x;
    __syncthreads();
    if (t < 32) {
        int y = wsum[t];
#pragma unroll
        for (int d = 1; d < 32; d <<= 1) {
            int z = __shfl_up_sync(0xffffffffu, y, d);
            if (t >= d) y += z;
        }
        wsum[t] = y;
    }
    __syncthreads();
    int woff = (w == 0) ? 0 : wsum[w - 1];
    int ex = woff + x - tsum;
    if (base + 0 < NSEG) g_scan[base + 0] = ex;
    ex += v0;
    if (base + 1 < NSEG) g_scan[base + 1] = ex;
    ex += v1;
    if (base + 2 < NSEG) g_scan[base + 2] = ex;
    ex += v2;
    if (base + 3 < NSEG) g_scan[base + 3] = ex;
    if (t == 0) g_bsum[b] = wsum[31];
}

// Exclusive scan of the NB2 block sums (single block of 256).
__global__ void scan_block_kernel() {
    __shared__ int wsum[8];
    int t = threadIdx.x;
    int v = (t < NB2) ? g_bsum[t] : 0;
    int lane = t & 31, w = t >> 5;
    int x = v;
#pragma unroll
    for (int d = 1; d < 32; d <<= 1) {
        int y = __shfl_up_sync(0xffffffffu, x, d);
        if (lane >= d) x += y;
    }
    if (lane == 31) wsum[w] = x;
    __syncthreads();
    if (t < 8) {
        int y = wsum[t];
#pragma unroll
        for (int d = 1; d < 8; d <<= 1) {
            int z = __shfl_up_sync(0xffu, y, d, 8);
            if (t >= d) y += z;
        }
        wsum[t] = y;
    }
    __syncthreads();
    int woff = (w == 0) ? 0 : wsum[w - 1];
    if (t < NB2) g_boff[t] = woff + x - v;
}

__global__ void scan_finish_kernel() {
    int i = blockIdx.x * blockDim.x + threadIdx.x;
    if (i < NSEG) {
        int r = g_scan[i] + g_boff[i >> 12];
        g_rp2[i] = r;
        g_cur[i] = r;
    }
    if (i == 0) g_rp2[NSEG] = NNZ_E;
}

__global__ void scatter_kernel(const int* __restrict__ rows,
                               const int* __restrict__ cols,
                               const float* __restrict__ vals) {
    int e = blockIdx.x * blockDim.x + threadIdx.x;
    if (e >= NNZ_E) return;
    int r = __ldg(rows + e);
    int c = __ldg(cols + e);
    float v = __ldg(vals + e);
    int t = (c >= TSPLIT);
    int pos = atomicAdd(&g_cur[r * NTILES + t], 1);
    g_csv[pos] = make_int2(c, __float_as_int(v));
}

// ---------------------------------------------------------------------------
// SpMM pass over column tile 0 (cols < TSPLIT): half-warp per row, exclusive
// ownership, write-only into g_side (streaming stores).
// ---------------------------------------------------------------------------
__global__ void __launch_bounds__(256)
spmm_pass_kernel(int pp) {
    int gtid = blockIdx.x * blockDim.x + threadIdx.x;
    int r = gtid >> 4;
    if (r >= NTOT) return;
    int j = threadIdx.x & 15;
    unsigned hmask = 0xFFFFu << (threadIdx.x & 16);
    ull pol = mk_evict_last();

    const float4* x4 = (const float4*)g_ego[pp];
    float4* side4 = (float4*)g_side;

    int s = __ldg(g_rp2 + r * NTILES);
    int e = __ldg(g_rp2 + r * NTILES + 1);

    float4 acc = make_float4(0.f, 0.f, 0.f, 0.f);
    for (int p = s; p < e; p += 16) {
        int idx = p + j;
        int cj = -1; float vj = 0.f;
        if (idx < e) {
            int2 cv = __ldcs(g_csv + idx);
            cj = cv.x; vj = __int_as_float(cv.y);
        }
#pragma unroll
        for (int q = 0; q < 16; q++) {
            int cc   = __shfl_sync(hmask, cj, q, 16);
            float vv = __shfl_sync(hmask, vj, q, 16);
            if (cc >= 0) {
                float4 g4 = ldg_el(x4 + (size_t)cc * 16 + j, pol);
                acc.x += vv * g4.x;
                acc.y += vv * g4.y;
                acc.z += vv * g4.z;
                acc.w += vv * g4.w;
            }
        }
    }
    __stcs(side4 + (size_t)r * 16 + j, acc);
}

// ---------------------------------------------------------------------------
// Fused: tile-1 SpMM (seeded with g_side partial) -> smem tiles ->
// GC/Bi GEMM (FFMA2) + lrelu + row-L2-normalize -> out + ego_next.
// 512 threads/block, <=64 regs (launch_bounds) -> 2 blocks/SM = 32 warps/SM.
// Chunk = 64 rows: 32 half-warps x 2 rows; thread tile = 2 nodes x 4 dims;
// norm phase: 8 threads per row.
// ---------------------------------------------------------------------------
__global__ void __launch_bounds__(512, 2)
fused_layer_kernel(const float* __restrict__ gw,
                   const float* __restrict__ gb,
                   const float* __restrict__ bw,
                   const float* __restrict__ bb,
                   float* __restrict__ out,
                   int col_off, int pp) {
    extern __shared__ float sh[];
    float* s_wgc  = sh;                 // 4096: wT[k*64+d]
    float* s_wbi  = sh + 4096;          // 4096
    float* s_side = sh + 8192;          // 64*68
    float* s_prod = sh + 8192 + 4352;   // 64*68 (reused as e-buffer)

    const float*  ego = g_ego[pp];
    float*   ego_next = g_ego[pp ^ 1];
    const float4* x4  = (const float4*)ego;
    const float4* side4 = (const float4*)g_side;

    int t = threadIdx.x;
    int j = t & 15;
    int h = t >> 4;                       // half-warp id 0..31
    unsigned hmask = 0xFFFFu << (t & 16);
    ull pol = mk_evict_last();

    for (int idx = t; idx < 4096; idx += 512) {
        int d = idx & 63, k = idx >> 6;
        s_wgc[k * 64 + d] = gw[d * 64 + k];
        s_wbi[k * 64 + d] = bw[d * 64 + k];
    }

    const int d0 = (t & 15) * 4;
    const int n0 = (t >> 4) * 2;          // 2 nodes per thread
    ull bg2[2], bb2[2];
#pragma unroll
    for (int p = 0; p < 2; p++) {
        bg2[p] = pack2(__ldg(gb + d0 + 2 * p), __ldg(gb + d0 + 2 * p + 1));
        bb2[p] = pack2(__ldg(bb + d0 + 2 * p), __ldg(bb + d0 + 2 * p + 1));
    }

    for (int c = blockIdx.x; c < CHUNKS; c += gridDim.x) {
        __syncthreads();
        int base = c * 64;

        // ---- Phase 1: tile-1 SpMM seeded with side partial (2 rows/half-warp) ----
#pragma unroll
        for (int i = 0; i < 2; i++) {
            int r = base + h * 2 + i;
            int s = __ldg(g_rp2 + r * NTILES + 1);
            int e = __ldg(g_rp2 + r * NTILES + 2);
            float4 acc = __ldcs(side4 + (size_t)r * 16 + j);
            for (int p = s; p < e; p += 16) {
                int idx = p + j;
                int cj = -1; float vj = 0.f;
                if (idx < e) {
                    int2 cv = __ldcs(g_csv + idx);
                    cj = cv.x; vj = __int_as_float(cv.y);
                }
#pragma unroll
                for (int q = 0; q < 16; q++) {
                    int cc   = __shfl_sync(hmask, cj, q, 16);
                    float vv = __shfl_sync(hmask, vj, q, 16);
                    if (cc >= 0) {
                        float4 g4 = ldg_el(x4 + (size_t)cc * 16 + j, pol);
                        acc.x += vv * g4.x;
                        acc.y += vv * g4.y;
                        acc.z += vv * g4.z;
                        acc.w += vv * g4.w;
                    }
                }
            }
            float4 ev = __ldg(x4 + (size_t)r * 16 + j);
            int node = h * 2 + i;
            *(float4*)&s_side[node * 68 + j * 4] = acc;
            *(float4*)&s_prod[node * 68 + j * 4] =
                make_float4(acc.x * ev.x, acc.y * ev.y, acc.z * ev.z, acc.w * ev.w);
        }
        __syncthreads();

        // ---- Phase 2: dense GC/Bi GEMM via packed f32x2 (2 nodes x 4 dims) ----
        ull accg2[2][2], accb2[2][2];
#pragma unroll
        for (int i = 0; i < 2; i++)
#pragma unroll
            for (int p = 0; p < 2; p++) {
                accg2[i][p] = bg2[p];
                accb2[i][p] = bb2[p];
            }

#pragma unroll 8
        for (int k = 0; k < 64; k++) {
            const ull* wgp = (const ull*)&s_wgc[k * 64 + d0];
            const ull* wbp = (const ull*)&s_wbi[k * 64 + d0];
            ull wg0 = wgp[0], wg1 = wgp[1];
            ull wb0 = wbp[0], wb1 = wbp[1];
#pragma unroll
            for (int i = 0; i < 2; i++) {
                float sv = s_side[(n0 + i) * 68 + k];
                float pv = s_prod[(n0 + i) * 68 + k];
                ull sv2 = pack2(sv, sv);
                ull pv2 = pack2(pv, pv);
                accg2[i][0] = fma2(sv2, wg0, accg2[i][0]);
                accg2[i][1] = fma2(sv2, wg1, accg2[i][1]);
                accb2[i][0] = fma2(pv2, wb0, accb2[i][0]);
                accb2[i][1] = fma2(pv2, wb1, accb2[i][1]);
            }
        }
        __syncthreads();

        // e = lrelu(gc) + lrelu(bi) into smem (reuse s_prod)
#pragma unroll
        for (int i = 0; i < 2; i++)
#pragma unroll
            for (int p = 0; p < 2; p++) {
                float2 a = unpack2(accg2[i][p]);
                float2 b = unpack2(accb2[i][p]);
                float e0 = fmaxf(a.x, 0.01f * a.x) + fmaxf(b.x, 0.01f * b.x);
                float e1 = fmaxf(a.y, 0.01f * a.y) + fmaxf(b.y, 0.01f * b.y);
                s_prod[(n0 + i) * 68 + d0 + 2 * p]     = e0;
                s_prod[(n0 + i) * 68 + d0 + 2 * p + 1] = e1;
            }
        __syncthreads();

        // Row norms + global writes: 8 threads/row (node = t/8, oct = t%8)
        int node = t >> 3, oc = t & 7;
        float ss = 0.f;
#pragma unroll
        for (int m = 0; m < 8; m++) {
            float v = s_prod[node * 68 + oc * 8 + m];
            ss += v * v;
        }
        ss += __shfl_xor_sync(0xffffffffu, ss, 1);
        ss += __shfl_xor_sync(0xffffffffu, ss, 2);
        ss += __shfl_xor_sync(0xffffffffu, ss, 4);
        float inv = 1.f / fmaxf(sqrtf(ss), 1e-12f);

        size_t gnode = (size_t)(base + node);
#pragma unroll
        for (int m = 0; m < 8; m += 4) {
            float4 v = *(const float4*)&s_prod[node * 68 + oc * 8 + m];
            *(float4*)&ego_next[gnode * 64 + oc * 8 + m] = v;
            float4 vn = make_float4(v.x * inv, v.y * inv, v.z * inv, v.w * inv);
            __stcs((float4*)&out[gnode * 256 + col_off + oc * 8 + m], vn);
        }
    }
}

// ---------------------------------------------------------------------------
extern "C" void kernel_launch(void* const* d_in, const int* in_sizes, int n_in,
                              void* d_out, int out_size) {
    const int*   rows = (const int*)d_in[0];
    const int*   cols = (const int*)d_in[1];
    const float* vals = (const float*)d_in[2];
    const float* ue   = (const float*)d_in[3];
    const float* ie   = (const float*)d_in[4];
    const float* gw   = (const float*)d_in[5];
    const float* gb   = (const float*)d_in[6];
    const float* bw   = (const float*)d_in[7];
    const float* bb   = (const float*)d_in[8];
    float* out = (float*)d_out;

    const int smem_bytes = (4096 * 2 + 4352 * 2) * 4;  // 67584 B
    cudaFuncSetAttribute(fused_layer_kernel,
                         cudaFuncAttributeMaxDynamicSharedMemorySize, smem_bytes);

    init_kernel<<<(NTOT * DIM + 255) / 256, 256>>>(ue, ie, out);

    // ---- (row, col-tile)-sorted edge list build (once; reused by all layers) ----
    zero_cnt_kernel<<<(NSEG + 255) / 256, 256>>>();
    hist_kernel<<<(NNZ_E + 255) / 256, 256>>>(rows, cols);
    scan_local_kernel<<<NB2, 1024>>>();
    scan_block_kernel<<<1, 256>>>();
    scan_finish_kernel<<<(NSEG + 255) / 256, 256>>>();
    scatter_kernel<<<(NNZ_E + 255) / 256, 256>>>(rows, cols, vals);

    // ---- 3 layers: tile-0 pass + fused(tile-1 + dense) ----
    const int pass_blocks = (NTOT * 16 + 255) / 256;  // one half-warp per row
    for (int i = 0; i < NLAYERS; i++) {
        int pp = i & 1;
        spmm_pass_kernel<<<pass_blocks, 256>>>(pp);
        fused_layer_kernel<<<CHUNKS, 512, smem_bytes>>>(
            gw + i * 4096, gb + i * 64, bw + i * 4096, bb + i * 64,
            out, (i + 1) * 64, pp);
    }
}

// round 14
// speedup vs baseline: 1.1046x; 1.0278x over previous
#include <cuda_runtime.h>
#include <cuda_fp16.h>

#define N_USERS_C 200000
#define NTOT      400000
#define DIM       64
#define NNZ_E     12800000
#define NLAYERS   3
#define CHUNKS    (NTOT / 64)

#define NTILES    2
#define TSPLIT    200000
#define NSEG      (NTOT * NTILES)            // 800,000
#define NB2       ((NSEG + 4095) / 4096)     // 196

typedef unsigned long long ull;

// ---- device-global scratch (allocation-free rule) ----
__device__ float   g_ego[2][(size_t)NTOT * DIM];   // fp32 ego (ping-pong)
__device__ __half2 g_egoh[2][(size_t)NTOT * 32];   // fp16 shadow (gather source)
__device__ float g_side[(size_t)NTOT * DIM];
__device__ int   g_cnt[NSEG];
__device__ int   g_scan[NSEG];
__device__ int   g_rp2[NSEG + 1];
__device__ int   g_cur[NSEG];
__device__ int   g_bsum[NB2];
__device__ int   g_boff[NB2];
__device__ int2  g_csv[NNZ_E];               // (col, float-bits of val)

// L2 evict-last policy + hinted 64-bit fp16 gather
__device__ __forceinline__ ull mk_evict_last() {
    ull pol;
    asm("createpolicy.fractional.L2::evict_last.b64 %0, 1.0;" : "=l"(pol));
    return pol;
}
__device__ __forceinline__ uint2 ldg_h(const uint2* p, ull pol) {
    uint2 r;
    asm volatile("ld.global.nc.L2::cache_hint.v2.u32 {%0,%1}, [%2], %3;"
                 : "=r"(r.x), "=r"(r.y) : "l"(p), "l"(pol));
    return r;
}

// Packed f32x2 helpers (FFMA2 — only reachable via PTX on sm_103a)
__device__ __forceinline__ ull pack2(float lo, float hi) {
    ull r; asm("mov.b64 %0, {%1,%2};" : "=l"(r) : "f"(lo), "f"(hi)); return r;
}
__device__ __forceinline__ ull fma2(ull a, ull b, ull c) {
    ull d; asm("fma.rn.f32x2 %0, %1, %2, %3;" : "=l"(d) : "l"(a), "l"(b), "l"(c));
    return d;
}
__device__ __forceinline__ float2 unpack2(ull v) {
    float2 r; asm("mov.b64 {%0,%1}, %2;" : "=f"(r.x), "=f"(r.y) : "l"(v)); return r;
}

// ---------------------------------------------------------------------------
// Init: ego0 (fp32 + fp16 shadow) and layer-0 columns of out. Thread per pair.
// ---------------------------------------------------------------------------
__global__ void init_kernel(const float* __restrict__ ue,
                            const float* __restrict__ ie,
                            float* __restrict__ out) {
    int idx = blockIdx.x * blockDim.x + threadIdx.x;  // pair index
    if (idx >= NTOT * 32) return;
    int node = idx >> 5;
    int dp = idx & 31;
    const float2* src = (node < N_USERS_C)
        ? (const float2*)ue + idx
        : (const float2*)ie + (idx - N_USERS_C * 32);
    float2 v = __ldg(src);
    *(float2*)&g_ego[0][(size_t)node * 64 + dp * 2] = v;
    g_egoh[0][(size_t)node * 32 + dp] = __floats2half2_rn(v.x, v.y);
    *(float2*)&out[(size_t)node * 256 + dp * 2] = v;
}

__global__ void zero_cnt_kernel() {
    int i = blockIdx.x * blockDim.x + threadIdx.x;
    if (i < NSEG) g_cnt[i] = 0;
}

__global__ void hist_kernel(const int* __restrict__ rows,
                            const int* __restrict__ cols) {
    int e = blockIdx.x * blockDim.x + threadIdx.x;
    if (e >= NNZ_E) return;
    int r = __ldg(rows + e);
    int c = __ldg(cols + e);
    int t = (c >= TSPLIT);
    atomicAdd(&g_cnt[r * NTILES + t], 1);
}

// Per-block exclusive scan of 4096 counts (1024 thr x 4); block total to g_bsum.
__global__ void scan_local_kernel() {
    __shared__ int wsum[32];
    int b = blockIdx.x, t = threadIdx.x;
    int base = b * 4096 + t * 4;
    int v0 = 0, v1 = 0, v2 = 0, v3 = 0;
    if (base + 0 < NSEG) v0 = g_cnt[base + 0];
    if (base + 1 < NSEG) v1 = g_cnt[base + 1];
    if (base + 2 < NSEG) v2 = g_cnt[base + 2];
    if (base + 3 < NSEG) v3 = g_cnt[base + 3];
    int tsum = v0 + v1 + v2 + v3;
    int lane = t & 31, w = t >> 5;
    int x = tsum;
#pragma unroll
    for (int d = 1; d < 32; d <<= 1) {
        int y = __shfl_up_sync(0xffffffffu, x, d);
        if (lane >= d) x += y;
    }
    if (lane == 31) wsum[w] = x;
    __syncthreads();
    if (t < 32) {
        int y = wsum[t];
#pragma unroll
        for (int d = 1; d < 32; d <<= 1) {
            int z = __shfl_up_sync(0xffffffffu, y, d);
            if (t >= d) y += z;
        }
        wsum[t] = y;
    }
    __syncthreads();
    int woff = (w == 0) ? 0 : wsum[w - 1];
    int ex = woff + x - tsum;
    if (base + 0 < NSEG) g_scan[base + 0] = ex;
    ex += v0;
    if (base + 1 < NSEG) g_scan[base + 1] = ex;
    ex += v1;
    if (base + 2 < NSEG) g_scan[base + 2] = ex;
    ex += v2;
    if (base + 3 < NSEG) g_scan[base + 3] = ex;
    if (t == 0) g_bsum[b] = wsum[31];
}

// Exclusive scan of the NB2 block sums (single block of 256).
__global__ void scan_block_kernel() {
    __shared__ int wsum[8];
    int t = threadIdx.x;
    int v = (t < NB2) ? g_bsum[t] : 0;
    int lane = t & 31, w = t >> 5;
    int x = v;
#pragma unroll
    for (int d = 1; d < 32; d <<= 1) {
        int y = __shfl_up_sync(0xffffffffu, x, d);
        if (lane >= d) x += y;
    }
    if (lane == 31) wsum[w] = x;
    __syncthreads();
    if (t < 8) {
        int y = wsum[t];
#pragma unroll
        for (int d = 1; d < 8; d <<= 1) {
            int z = __shfl_up_sync(0xffu, y, d, 8);
            if (t >= d) y += z;
        }
        wsum[t] = y;
    }
    __syncthreads();
    int woff = (w == 0) ? 0 : wsum[w - 1];
    if (t < NB2) g_boff[t] = woff + x - v;
}

__global__ void scan_finish_kernel() {
    int i = blockIdx.x * blockDim.x + threadIdx.x;
    if (i < NSEG) {
        int r = g_scan[i] + g_boff[i >> 12];
        g_rp2[i] = r;
        g_cur[i] = r;
    }
    if (i == 0) g_rp2[NSEG] = NNZ_E;
}

__global__ void scatter_kernel(const int* __restrict__ rows,
                               const int* __restrict__ cols,
                               const float* __restrict__ vals) {
    int e = blockIdx.x * blockDim.x + threadIdx.x;
    if (e >= NNZ_E) return;
    int r = __ldg(rows + e);
    int c = __ldg(cols + e);
    float v = __ldg(vals + e);
    int t = (c >= TSPLIT);
    int pos = atomicAdd(&g_cur[r * NTILES + t], 1);
    __stcs(g_csv + pos, make_int2(c, __float_as_int(v)));
}

// ---------------------------------------------------------------------------
// SpMM pass over column tile 0 (cols < TSPLIT): half-warp per row, exclusive
// ownership, fp16 gather (1 L2 line/row) / fp32 accumulate, streaming stores.
// ---------------------------------------------------------------------------
__global__ void __launch_bounds__(256)
spmm_pass_kernel(int pp) {
    int gtid = blockIdx.x * blockDim.x + threadIdx.x;
    int r = gtid >> 4;
    if (r >= NTOT) return;
    int j = threadIdx.x & 15;
    unsigned hmask = 0xFFFFu << (threadIdx.x & 16);
    ull pol = mk_evict_last();

    const uint2* xh = (const uint2*)g_egoh[pp];   // 16 uint2 per row
    float4* side4 = (float4*)g_side;

    int s = __ldg(g_rp2 + r * NTILES);
    int e = __ldg(g_rp2 + r * NTILES + 1);

    float4 acc = make_float4(0.f, 0.f, 0.f, 0.f);
    for (int p = s; p < e; p += 16) {
        int idx = p + j;
        int cj = -1; float vj = 0.f;
        if (idx < e) {
            int2 cv = __ldcs(g_csv + idx);
            cj = cv.x; vj = __int_as_float(cv.y);
        }
#pragma unroll
        for (int q = 0; q < 16; q++) {
            int cc   = __shfl_sync(hmask, cj, q, 16);
            float vv = __shfl_sync(hmask, vj, q, 16);
            if (cc >= 0) {
                uint2 u = ldg_h(xh + (size_t)cc * 16 + j, pol);
                float2 fa = __half22float2(*(__half2*)&u.x);
                float2 fb = __half22float2(*(__half2*)&u.y);
                acc.x += vv * fa.x;
                acc.y += vv * fa.y;
                acc.z += vv * fb.x;
                acc.w += vv * fb.y;
            }
        }
    }
    __stcs(side4 + (size_t)r * 16 + j, acc);
}

// ---------------------------------------------------------------------------
// Fused: tile-1 SpMM (fp16 gather, seeded with g_side partial) -> smem tiles ->
// GC/Bi GEMM (FFMA2) + lrelu + row-L2-normalize -> out + ego_next (+fp16 shadow).
// 512 threads/block, 2 blocks/SM; chunk = 64 rows; 32 half-warps x 2 rows.
// ---------------------------------------------------------------------------
__global__ void __launch_bounds__(512, 2)
fused_layer_kernel(const float* __restrict__ gw,
                   const float* __restrict__ gb,
                   const float* __restrict__ bw,
                   const float* __restrict__ bb,
                   float* __restrict__ out,
                   int col_off, int pp) {
    extern __shared__ float sh[];
    float* s_wgc  = sh;                 // 4096: wT[k*64+d]
    float* s_wbi  = sh + 4096;          // 4096
    float* s_side = sh + 8192;          // 64*68
    float* s_prod = sh + 8192 + 4352;   // 64*68 (reused as e-buffer)

    const float*  ego = g_ego[pp];
    float*   ego_next = g_ego[pp ^ 1];
    const float4* x4  = (const float4*)ego;
    const uint2*  xh  = (const uint2*)g_egoh[pp];
    __half2* egoh_next = g_egoh[pp ^ 1];
    const float4* side4 = (const float4*)g_side;

    int t = threadIdx.x;
    int j = t & 15;
    int h = t >> 4;                       // half-warp id 0..31
    unsigned hmask = 0xFFFFu << (t & 16);
    ull pol = mk_evict_last();

    for (int idx = t; idx < 4096; idx += 512) {
        int d = idx & 63, k = idx >> 6;
        s_wgc[k * 64 + d] = gw[d * 64 + k];
        s_wbi[k * 64 + d] = bw[d * 64 + k];
    }

    const int d0 = (t & 15) * 4;
    const int n0 = (t >> 4) * 2;          // 2 nodes per thread
    ull bg2[2], bb2[2];
#pragma unroll
    for (int p = 0; p < 2; p++) {
        bg2[p] = pack2(__ldg(gb + d0 + 2 * p), __ldg(gb + d0 + 2 * p + 1));
        bb2[p] = pack2(__ldg(bb + d0 + 2 * p), __ldg(bb + d0 + 2 * p + 1));
    }

    for (int c = blockIdx.x; c < CHUNKS; c += gridDim.x) {
        __syncthreads();
        int base = c * 64;

        // ---- Phase 1: tile-1 SpMM seeded with side partial (2 rows/half-warp) ----
#pragma unroll
        for (int i = 0; i < 2; i++) {
            int r = base + h * 2 + i;
            int s = __ldg(g_rp2 + r * NTILES + 1);
            int e = __ldg(g_rp2 + r * NTILES + 2);
            float4 acc = __ldcs(side4 + (size_t)r * 16 + j);
            for (int p = s; p < e; p += 16) {
                int idx = p + j;
                int cj = -1; float vj = 0.f;
                if (idx < e) {
                    int2 cv = __ldcs(g_csv + idx);
                    cj = cv.x; vj = __int_as_float(cv.y);
                }
#pragma unroll
                for (int q = 0; q < 16; q++) {
                    int cc   = __shfl_sync(hmask, cj, q, 16);
                    float vv = __shfl_sync(hmask, vj, q, 16);
                    if (cc >= 0) {
                        uint2 u = ldg_h(xh + (size_t)cc * 16 + j, pol);
                        float2 fa = __half22float2(*(__half2*)&u.x);
                        float2 fb = __half22float2(*(__half2*)&u.y);
                        acc.x += vv * fa.x;
                        acc.y += vv * fa.y;
                        acc.z += vv * fb.x;
                        acc.w += vv * fb.y;
                    }
                }
            }
            float4 ev = __ldg(x4 + (size_t)r * 16 + j);   // fp32 ego for Bi branch
            int node = h * 2 + i;
            *(float4*)&s_side[node * 68 + j * 4] = acc;
            *(float4*)&s_prod[node * 68 + j * 4] =
                make_float4(acc.x * ev.x, acc.y * ev.y, acc.z * ev.z, acc.w * ev.w);
        }
        __syncthreads();

        // ---- Phase 2: dense GC/Bi GEMM via packed f32x2 (2 nodes x 4 dims) ----
        ull accg2[2][2], accb2[2][2];
#pragma unroll
        for (int i = 0; i < 2; i++)
#pragma unroll
            for (int p = 0; p < 2; p++) {
                accg2[i][p] = bg2[p];
                accb2[i][p] = bb2[p];
            }

#pragma unroll 8
        for (int k = 0; k < 64; k++) {
            const ull* wgp = (const ull*)&s_wgc[k * 64 + d0];
            const ull* wbp = (const ull*)&s_wbi[k * 64 + d0];
            ull wg0 = wgp[0], wg1 = wgp[1];
            ull wb0 = wbp[0], wb1 = wbp[1];
#pragma unroll
            for (int i = 0; i < 2; i++) {
                float sv = s_side[(n0 + i) * 68 + k];
                float pv = s_prod[(n0 + i) * 68 + k];
                ull sv2 = pack2(sv, sv);
                ull pv2 = pack2(pv, pv);
                accg2[i][0] = fma2(sv2, wg0, accg2[i][0]);
                accg2[i][1] = fma2(sv2, wg1, accg2[i][1]);
                accb2[i][0] = fma2(pv2, wb0, accb2[i][0]);
                accb2[i][1] = fma2(pv2, wb1, accb2[i][1]);
            }
        }
        __syncthreads();

        // e = lrelu(gc) + lrelu(bi) into smem (reuse s_prod)
#pragma unroll
        for (int i = 0; i < 2; i++)
#pragma unroll
            for (int p = 0; p < 2; p++) {
                float2 a = unpack2(accg2[i][p]);
                float2 b = unpack2(accb2[i][p]);
                float e0 = fmaxf(a.x, 0.01f * a.x) + fmaxf(b.x, 0.01f * b.x);
                float e1 = fmaxf(a.y, 0.01f * a.y) + fmaxf(b.y, 0.01f * b.y);
                s_prod[(n0 + i) * 68 + d0 + 2 * p]     = e0;
                s_prod[(n0 + i) * 68 + d0 + 2 * p + 1] = e1;
            }
        __syncthreads();

        // Row norms + global writes: 8 threads/row (node = t/8, oct = t%8)
        int node = t >> 3, oc = t & 7;
        float ss = 0.f;
#pragma unroll
        for (int m = 0; m < 8; m++) {
            float v = s_prod[node * 68 + oc * 8 + m];
            ss += v * v;
        }
        ss += __shfl_xor_sync(0xffffffffu, ss, 1);
        ss += __shfl_xor_sync(0xffffffffu, ss, 2);
        ss += __shfl_xor_sync(0xffffffffu, ss, 4);
        float inv = 1.f / fmaxf(sqrtf(ss), 1e-12f);

        size_t gnode = (size_t)(base + node);
        unsigned hb[4];
#pragma unroll
        for (int m = 0; m < 8; m += 4) {
            float4 v = *(const float4*)&s_prod[node * 68 + oc * 8 + m];
            *(float4*)&ego_next[gnode * 64 + oc * 8 + m] = v;
            __half2 h0 = __floats2half2_rn(v.x, v.y);
            __half2 h1 = __floats2half2_rn(v.z, v.w);
            hb[m / 2]     = *(unsigned*)&h0;
            hb[m / 2 + 1] = *(unsigned*)&h1;
            float4 vn = make_float4(v.x * inv, v.y * inv, v.z * inv, v.w * inv);
            __stcs((float4*)&out[gnode * 256 + col_off + oc * 8 + m], vn);
        }
        // fp16 shadow for next layer's gathers (one 16B store: 8 dims)
        *(uint4*)&egoh_next[gnode * 32 + oc * 4] = make_uint4(hb[0], hb[1], hb[2], hb[3]);
    }
}

// ---------------------------------------------------------------------------
extern "C" void kernel_launch(void* const* d_in, const int* in_sizes, int n_in,
                              void* d_out, int out_size) {
    const int*   rows = (const int*)d_in[0];
    const int*   cols = (const int*)d_in[1];
    const float* vals = (const float*)d_in[2];
    const float* ue   = (const float*)d_in[3];
    const float* ie   = (const float*)d_in[4];
    const float* gw   = (const float*)d_in[5];
    const float* gb   = (const float*)d_in[6];
    const float* bw   = (const float*)d_in[7];
    const float* bb   = (const float*)d_in[8];
    float* out = (float*)d_out;

    const int smem_bytes = (4096 * 2 + 4352 * 2) * 4;  // 67584 B
    cudaFuncSetAttribute(fused_layer_kernel,
                         cudaFuncAttributeMaxDynamicSharedMemorySize, smem_bytes);

    init_kernel<<<(NTOT * 32 + 255) / 256, 256>>>(ue, ie, out);

    // ---- (row, col-tile)-sorted edge list build (once; reused by all layers) ----
    zero_cnt_kernel<<<(NSEG + 255) / 256, 256>>>();
    hist_kernel<<<(NNZ_E + 255) / 256, 256>>>(rows, cols);
    scan_local_kernel<<<NB2, 1024>>>();
    scan_block_kernel<<<1, 256>>>();
    scan_finish_kernel<<<(NSEG + 255) / 256, 256>>>();
    scatter_kernel<<<(NNZ_E + 255) / 256, 256>>>(rows, cols, vals);

    // ---- 3 layers: tile-0 pass + fused(tile-1 + dense) ----
    const int pass_blocks = (NTOT * 16 + 255) / 256;  // one half-warp per row
    for (int i = 0; i < NLAYERS; i++) {
        int pp = i & 1;
        spmm_pass_kernel<<<pass_blocks, 256>>>(pp);
        fused_layer_kernel<<<CHUNKS, 512, smem_bytes>>>(
            gw + i * 4096, gb + i * 64, bw + i * 4096, bb + i * 64,
            out, (i + 1) * 64, pp);
    }
}

// round 15
// speedup vs baseline: 1.3412x; 1.2142x over previous
#include <cuda_runtime.h>
#include <cuda_fp16.h>

#define N_USERS_C 200000
#define NTOT      400000
#define DIM       64
#define NNZ_E     12800000
#define NLAYERS   3
#define CHUNKS    (NTOT / 64)
#define FUSED_GRID 296   // 2 blocks/SM x 148 SM: weights loaded once per block

#define NTILES    2
#define TSPLIT    200000
#define NSEG      (NTOT * NTILES)            // 800,000
#define NB2       ((NSEG + 4095) / 4096)     // 196

typedef unsigned long long ull;

// ---- device-global scratch (allocation-free rule) ----
__device__ float   g_ego[2][(size_t)NTOT * DIM];   // fp32 ego (ping-pong)
__device__ __half2 g_egoh[2][(size_t)NTOT * 32];   // fp16 shadow (gather source)
__device__ float g_side[(size_t)NTOT * DIM];
__device__ int   g_cnt[NSEG];
__device__ int   g_scan[NSEG];
__device__ int   g_rp2[NSEG + 1];
__device__ int   g_cur[NSEG];
__device__ int   g_bsum[NB2];
__device__ int   g_boff[NB2];
__device__ int2  g_csv[NNZ_E];               // (col, float-bits of val)

// L2 evict-last policy + hinted 64-bit fp16 gather
__device__ __forceinline__ ull mk_evict_last() {
    ull pol;
    asm("createpolicy.fractional.L2::evict_last.b64 %0, 1.0;" : "=l"(pol));
    return pol;
}
__device__ __forceinline__ uint2 ldg_h(const uint2* p, ull pol) {
    uint2 r;
    asm volatile("ld.global.nc.L2::cache_hint.v2.u32 {%0,%1}, [%2], %3;"
                 : "=r"(r.x), "=r"(r.y) : "l"(p), "l"(pol));
    return r;
}

// Packed f32x2 helpers (FFMA2 — only reachable via PTX on sm_103a)
__device__ __forceinline__ ull pack2(float lo, float hi) {
    ull r; asm("mov.b64 %0, {%1,%2};" : "=l"(r) : "f"(lo), "f"(hi)); return r;
}
__device__ __forceinline__ ull fma2(ull a, ull b, ull c) {
    ull d; asm("fma.rn.f32x2 %0, %1, %2, %3;" : "=l"(d) : "l"(a), "l"(b), "l"(c));
    return d;
}
__device__ __forceinline__ float2 unpack2(ull v) {
    float2 r; asm("mov.b64 {%0,%1}, %2;" : "=f"(r.x), "=f"(r.y) : "l"(v)); return r;
}

// ---------------------------------------------------------------------------
// Init: ego0 (fp32 + fp16 shadow) and layer-0 columns of out. Thread per pair.
// ---------------------------------------------------------------------------
__global__ void init_kernel(const float* __restrict__ ue,
                            const float* __restrict__ ie,
                            float* __restrict__ out) {
    int idx = blockIdx.x * blockDim.x + threadIdx.x;  // pair index
    if (idx >= NTOT * 32) return;
    int node = idx >> 5;
    int dp = idx & 31;
    const float2* src = (node < N_USERS_C)
        ? (const float2*)ue + idx
        : (const float2*)ie + (idx - N_USERS_C * 32);
    float2 v = __ldg(src);
    *(float2*)&g_ego[0][(size_t)node * 64 + dp * 2] = v;
    g_egoh[0][(size_t)node * 32 + dp] = __floats2half2_rn(v.x, v.y);
    *(float2*)&out[(size_t)node * 256 + dp * 2] = v;
}

__global__ void zero_cnt_kernel() {
    int i = blockIdx.x * blockDim.x + threadIdx.x;
    if (i < NSEG) g_cnt[i] = 0;
}

__global__ void hist_kernel(const int* __restrict__ rows,
                            const int* __restrict__ cols) {
    int e = blockIdx.x * blockDim.x + threadIdx.x;
    if (e >= NNZ_E) return;
    int r = __ldg(rows + e);
    int c = __ldg(cols + e);
    int t = (c >= TSPLIT);
    atomicAdd(&g_cnt[r * NTILES + t], 1);
}

// Per-block exclusive scan of 4096 counts (1024 thr x 4); block total to g_bsum.
__global__ void scan_local_kernel() {
    __shared__ int wsum[32];
    int b = blockIdx.x, t = threadIdx.x;
    int base = b * 4096 + t * 4;
    int v0 = 0, v1 = 0, v2 = 0, v3 = 0;
    if (base + 0 < NSEG) v0 = g_cnt[base + 0];
    if (base + 1 < NSEG) v1 = g_cnt[base + 1];
    if (base + 2 < NSEG) v2 = g_cnt[base + 2];
    if (base + 3 < NSEG) v3 = g_cnt[base + 3];
    int tsum = v0 + v1 + v2 + v3;
    int lane = t & 31, w = t >> 5;
    int x = tsum;
#pragma unroll
    for (int d = 1; d < 32; d <<= 1) {
        int y = __shfl_up_sync(0xffffffffu, x, d);
        if (lane >= d) x += y;
    }
    if (lane == 31) wsum[w] = x;
    __syncthreads();
    if (t < 32) {
        int y = wsum[t];
#pragma unroll
        for (int d = 1; d < 32; d <<= 1) {
            int z = __shfl_up_sync(0xffffffffu, y, d);
            if (t >= d) y += z;
        }
        wsum[t] = y;
    }
    __syncthreads();
    int woff = (w == 0) ? 0 : wsum[w - 1];
    int ex = woff + x - tsum;
    if (base + 0 < NSEG) g_scan[base + 0] = ex;
    ex += v0;
    if (base + 1 < NSEG) g_scan[base + 1] = ex;
    ex += v1;
    if (base + 2 < NSEG) g_scan[base + 2] = ex;
    ex += v2;
    if (base + 3 < NSEG) g_scan[base + 3] = ex;
    if (t == 0) g_bsum[b] = wsum[31];
}

// Exclusive scan of the NB2 block sums (single block of 256).
__global__ void scan_block_kernel() {
    __shared__ int wsum[8];
    int t = threadIdx.x;
    int v = (t < NB2) ? g_bsum[t] : 0;
    int lane = t & 31, w = t >> 5;
    int x = v;
#pragma unroll
    for (int d = 1; d < 32; d <<= 1) {
        int y = __shfl_up_sync(0xffffffffu, x, d);
        if (lane >= d) x += y;
    }
    if (lane == 31) wsum[w] = x;
    __syncthreads();
    if (t < 8) {
        int y = wsum[t];
#pragma unroll
        for (int d = 1; d < 8; d <<= 1) {
            int z = __shfl_up_sync(0xffu, y, d, 8);
            if (t >= d) y += z;
        }
        wsum[t] = y;
    }
    __syncthreads();
    int woff = (w == 0) ? 0 : wsum[w - 1];
    if (t < NB2) g_boff[t] = woff + x - v;
}

__global__ void scan_finish_kernel() {
    int i = blockIdx.x * blockDim.x + threadIdx.x;
    if (i < NSEG) {
        int r = g_scan[i] + g_boff[i >> 12];
        g_rp2[i] = r;
        g_cur[i] = r;
    }
    if (i == 0) g_rp2[NSEG] = NNZ_E;
}

__global__ void scatter_kernel(const int* __restrict__ rows,
                               const int* __restrict__ cols,
                               const float* __restrict__ vals) {
    int e = blockIdx.x * blockDim.x + threadIdx.x;
    if (e >= NNZ_E) return;
    int r = __ldg(rows + e);
    int c = __ldg(cols + e);
    float v = __ldg(vals + e);
    int t = (c >= TSPLIT);
    int pos = atomicAdd(&g_cur[r * NTILES + t], 1);
    __stcs(g_csv + pos, make_int2(c, __float_as_int(v)));
}

// ---------------------------------------------------------------------------
// SpMM pass over column tile 0 (cols < TSPLIT): half-warp per row, exclusive
// ownership, fp16 gather (1 L2 line/row) / fp32 accumulate, streaming stores.
// ---------------------------------------------------------------------------
__global__ void __launch_bounds__(256)
spmm_pass_kernel(int pp) {
    int gtid = blockIdx.x * blockDim.x + threadIdx.x;
    int r = gtid >> 4;
    if (r >= NTOT) return;
    int j = threadIdx.x & 15;
    unsigned hmask = 0xFFFFu << (threadIdx.x & 16);
    ull pol = mk_evict_last();

    const uint2* xh = (const uint2*)g_egoh[pp];   // 16 uint2 per row
    float4* side4 = (float4*)g_side;

    int s = __ldg(g_rp2 + r * NTILES);
    int e = __ldg(g_rp2 + r * NTILES + 1);

    float4 acc = make_float4(0.f, 0.f, 0.f, 0.f);
    for (int p = s; p < e; p += 16) {
        int idx = p + j;
        int cj = -1; float vj = 0.f;
        if (idx < e) {
            int2 cv = __ldcs(g_csv + idx);
            cj = cv.x; vj = __int_as_float(cv.y);
        }
#pragma unroll
        for (int q = 0; q < 16; q++) {
            int cc   = __shfl_sync(hmask, cj, q, 16);
            float vv = __shfl_sync(hmask, vj, q, 16);
            if (cc >= 0) {
                uint2 u = ldg_h(xh + (size_t)cc * 16 + j, pol);
                float2 fa = __half22float2(*(__half2*)&u.x);
                float2 fb = __half22float2(*(__half2*)&u.y);
                acc.x += vv * fa.x;
                acc.y += vv * fa.y;
                acc.z += vv * fb.x;
                acc.w += vv * fb.y;
            }
        }
    }
    __stcs(side4 + (size_t)r * 16 + j, acc);
}

// ---------------------------------------------------------------------------
// Fused: tile-1 SpMM (fp16 gather, seeded with g_side partial) -> smem tiles ->
// GC/Bi GEMM (FFMA2) + lrelu + row-L2-normalize -> out + ego_next (+fp16 shadow).
// 512 threads/block, 2 blocks/SM; PERSISTENT grid (296 blocks): weights loaded
// and transposed ONCE per block, amortized over ~21 chunks.
// ---------------------------------------------------------------------------
__global__ void __launch_bounds__(512, 2)
fused_layer_kernel(const float* __restrict__ gw,
                   const float* __restrict__ gb,
                   const float* __restrict__ bw,
                   const float* __restrict__ bb,
                   float* __restrict__ out,
                   int col_off, int pp) {
    extern __shared__ float sh[];
    float* s_wgc  = sh;                 // 4096: wT[k*64+d]
    float* s_wbi  = sh + 4096;          // 4096
    float* s_side = sh + 8192;          // 64*68
    float* s_prod = sh + 8192 + 4352;   // 64*68 (reused as e-buffer)

    const float*  ego = g_ego[pp];
    float*   ego_next = g_ego[pp ^ 1];
    const float4* x4  = (const float4*)ego;
    const uint2*  xh  = (const uint2*)g_egoh[pp];
    __half2* egoh_next = g_egoh[pp ^ 1];
    const float4* side4 = (const float4*)g_side;

    int t = threadIdx.x;
    int j = t & 15;
    int h = t >> 4;                       // half-warp id 0..31
    unsigned hmask = 0xFFFFu << (t & 16);
    ull pol = mk_evict_last();

    // Weights: loaded once per persistent block
    for (int idx = t; idx < 4096; idx += 512) {
        int d = idx & 63, k = idx >> 6;
        s_wgc[k * 64 + d] = gw[d * 64 + k];
        s_wbi[k * 64 + d] = bw[d * 64 + k];
    }

    const int d0 = (t & 15) * 4;
    const int n0 = (t >> 4) * 2;          // 2 nodes per thread
    ull bg2[2], bb2[2];
#pragma unroll
    for (int p = 0; p < 2; p++) {
        bg2[p] = pack2(__ldg(gb + d0 + 2 * p), __ldg(gb + d0 + 2 * p + 1));
        bb2[p] = pack2(__ldg(bb + d0 + 2 * p), __ldg(bb + d0 + 2 * p + 1));
    }

    for (int c = blockIdx.x; c < CHUNKS; c += gridDim.x) {
        __syncthreads();
        int base = c * 64;

        // ---- Phase 1: tile-1 SpMM seeded with side partial (2 rows/half-warp) ----
#pragma unroll
        for (int i = 0; i < 2; i++) {
            int r = base + h * 2 + i;
            int s = __ldg(g_rp2 + r * NTILES + 1);
            int e = __ldg(g_rp2 + r * NTILES + 2);
            float4 acc = __ldcs(side4 + (size_t)r * 16 + j);
            for (int p = s; p < e; p += 16) {
                int idx = p + j;
                int cj = -1; float vj = 0.f;
                if (idx < e) {
                    int2 cv = __ldcs(g_csv + idx);
                    cj = cv.x; vj = __int_as_float(cv.y);
                }
#pragma unroll
                for (int q = 0; q < 16; q++) {
                    int cc   = __shfl_sync(hmask, cj, q, 16);
                    float vv = __shfl_sync(hmask, vj, q, 16);
                    if (cc >= 0) {
                        uint2 u = ldg_h(xh + (size_t)cc * 16 + j, pol);
                        float2 fa = __half22float2(*(__half2*)&u.x);
                        float2 fb = __half22float2(*(__half2*)&u.y);
                        acc.x += vv * fa.x;
                        acc.y += vv * fa.y;
                        acc.z += vv * fb.x;
                        acc.w += vv * fb.y;
                    }
                }
            }
            float4 ev = __ldg(x4 + (size_t)r * 16 + j);   // fp32 ego for Bi branch
            int node = h * 2 + i;
            *(float4*)&s_side[node * 68 + j * 4] = acc;
            *(float4*)&s_prod[node * 68 + j * 4] =
                make_float4(acc.x * ev.x, acc.y * ev.y, acc.z * ev.z, acc.w * ev.w);
        }
        __syncthreads();

        // ---- Phase 2: dense GC/Bi GEMM via packed f32x2 (2 nodes x 4 dims) ----
        ull accg2[2][2], accb2[2][2];
#pragma unroll
        for (int i = 0; i < 2; i++)
#pragma unroll
            for (int p = 0; p < 2; p++) {
                accg2[i][p] = bg2[p];
                accb2[i][p] = bb2[p];
            }

#pragma unroll 8
        for (int k = 0; k < 64; k++) {
            const ull* wgp = (const ull*)&s_wgc[k * 64 + d0];
            const ull* wbp = (const ull*)&s_wbi[k * 64 + d0];
            ull wg0 = wgp[0], wg1 = wgp[1];
            ull wb0 = wbp[0], wb1 = wbp[1];
#pragma unroll
            for (int i = 0; i < 2; i++) {
                float sv = s_side[(n0 + i) * 68 + k];
                float pv = s_prod[(n0 + i) * 68 + k];
                ull sv2 = pack2(sv, sv);
                ull pv2 = pack2(pv, pv);
                accg2[i][0] = fma2(sv2, wg0, accg2[i][0]);
                accg2[i][1] = fma2(sv2, wg1, accg2[i][1]);
                accb2[i][0] = fma2(pv2, wb0, accb2[i][0]);
                accb2[i][1] = fma2(pv2, wb1, accb2[i][1]);
            }
        }
        __syncthreads();

        // e = lrelu(gc) + lrelu(bi) into smem (reuse s_prod)
#pragma unroll
        for (int i = 0; i < 2; i++)
#pragma unroll
            for (int p = 0; p < 2; p++) {
                float2 a = unpack2(accg2[i][p]);
                float2 b = unpack2(accb2[i][p]);
                float e0 = fmaxf(a.x, 0.01f * a.x) + fmaxf(b.x, 0.01f * b.x);
                float e1 = fmaxf(a.y, 0.01f * a.y) + fmaxf(b.y, 0.01f * b.y);
                s_prod[(n0 + i) * 68 + d0 + 2 * p]     = e0;
                s_prod[(n0 + i) * 68 + d0 + 2 * p + 1] = e1;
            }
        __syncthreads();

        // Row norms + global writes: 8 threads/row (node = t/8, oct = t%8)
        int node = t >> 3, oc = t & 7;
        float ss = 0.f;
#pragma unroll
        for (int m = 0; m < 8; m++) {
            float v = s_prod[node * 68 + oc * 8 + m];
            ss += v * v;
        }
        ss += __shfl_xor_sync(0xffffffffu, ss, 1);
        ss += __shfl_xor_sync(0xffffffffu, ss, 2);
        ss += __shfl_xor_sync(0xffffffffu, ss, 4);
        float inv = 1.f / fmaxf(sqrtf(ss), 1e-12f);

        size_t gnode = (size_t)(base + node);
        unsigned hb[4];
#pragma unroll
        for (int m = 0; m < 8; m += 4) {
            float4 v = *(const float4*)&s_prod[node * 68 + oc * 8 + m];
            *(float4*)&ego_next[gnode * 64 + oc * 8 + m] = v;
            __half2 h0 = __floats2half2_rn(v.x, v.y);
            __half2 h1 = __floats2half2_rn(v.z, v.w);
            hb[m / 2]     = *(unsigned*)&h0;
            hb[m / 2 + 1] = *(unsigned*)&h1;
            float4 vn = make_float4(v.x * inv, v.y * inv, v.z * inv, v.w * inv);
            __stcs((float4*)&out[gnode * 256 + col_off + oc * 8 + m], vn);
        }
        // fp16 shadow for next layer's gathers (one 16B store: 8 dims)
        *(uint4*)&egoh_next[gnode * 32 + oc * 4] = make_uint4(hb[0], hb[1], hb[2], hb[3]);
    }
}

// ---------------------------------------------------------------------------
extern "C" void kernel_launch(void* const* d_in, const int* in_sizes, int n_in,
                              void* d_out, int out_size) {
    const int*   rows = (const int*)d_in[0];
    const int*   cols = (const int*)d_in[1];
    const float* vals = (const float*)d_in[2];
    const float* ue   = (const float*)d_in[3];
    const float* ie   = (const float*)d_in[4];
    const float* gw   = (const float*)d_in[5];
    const float* gb   = (const float*)d_in[6];
    const float* bw   = (const float*)d_in[7];
    const float* bb   = (const float*)d_in[8];
    float* out = (float*)d_out;

    const int smem_bytes = (4096 * 2 + 4352 * 2) * 4;  // 67584 B
    cudaFuncSetAttribute(fused_layer_kernel,
                         cudaFuncAttributeMaxDynamicSharedMemorySize, smem_bytes);

    init_kernel<<<(NTOT * 32 + 255) / 256, 256>>>(ue, ie, out);

    // ---- (row, col-tile)-sorted edge list build (once; reused by all layers) ----
    zero_cnt_kernel<<<(NSEG + 255) / 256, 256>>>();
    hist_kernel<<<(NNZ_E + 255) / 256, 256>>>(rows, cols);
    scan_local_kernel<<<NB2, 1024>>>();
    scan_block_kernel<<<1, 256>>>();
    scan_finish_kernel<<<(NSEG + 255) / 256, 256>>>();
    scatter_kernel<<<(NNZ_E + 255) / 256, 256>>>(rows, cols, vals);

    // ---- 3 layers: tile-0 pass + fused(tile-1 + dense, persistent grid) ----
    const int pass_blocks = (NTOT * 16 + 255) / 256;  // one half-warp per row
    for (int i = 0; i < NLAYERS; i++) {
        int pp = i & 1;
        spmm_pass_kernel<<<pass_blocks, 256>>>(pp);
        fused_layer_kernel<<<FUSED_GRID, 512, smem_bytes>>>(
            gw + i * 4096, gb + i * 64, bw + i * 4096, bb + i * 64,
            out, (i + 1) * 64, pp);
    }
}

// round 16
// speedup vs baseline: 1.3414x; 1.0002x over previous
#include <cuda_runtime.h>
#include <cuda_fp16.h>

#define N_USERS_C 200000
#define NTOT      400000
#define DIM       64
#define NNZ_E     12800000
#define NLAYERS   3
#define CHUNKS    (NTOT / 64)
#define FUSED_GRID 296   // 2 blocks/SM x 148 SM: weights loaded once per block

#define NTILES    2
#define TSPLIT    200000
#define NSEG      (NTOT * NTILES)            // 800,000
#define NB2       ((NSEG + 4095) / 4096)     // 196

typedef unsigned long long ull;

// ---- device-global scratch (allocation-free rule) ----
__device__ float   g_ego[2][(size_t)NTOT * DIM];   // fp32 ego (ping-pong)
__device__ __half2 g_egoh[2][(size_t)NTOT * 32];   // fp16 shadow (gather source)
__device__ float g_side[(size_t)NTOT * DIM];
__device__ int   g_cnt[NSEG];
__device__ int   g_scan[NSEG];
__device__ int   g_rp2[NSEG + 1];
__device__ int   g_cur[NSEG];
__device__ int   g_bsum[NB2];
__device__ int   g_boff[NB2];
__device__ int2  g_csv[NNZ_E];               // (col, float-bits of val)

// L2 evict-last policy + hinted 64-bit fp16 gather
__device__ __forceinline__ ull mk_evict_last() {
    ull pol;
    asm("createpolicy.fractional.L2::evict_last.b64 %0, 1.0;" : "=l"(pol));
    return pol;
}
__device__ __forceinline__ uint2 ldg_h(const uint2* p, ull pol) {
    uint2 r;
    asm volatile("ld.global.nc.L2::cache_hint.v2.u32 {%0,%1}, [%2], %3;"
                 : "=r"(r.x), "=r"(r.y) : "l"(p), "l"(pol));
    return r;
}

// Packed f32x2 helpers (FFMA2 — only reachable via PTX on sm_103a)
__device__ __forceinline__ ull pack2(float lo, float hi) {
    ull r; asm("mov.b64 %0, {%1,%2};" : "=l"(r) : "f"(lo), "f"(hi)); return r;
}
__device__ __forceinline__ ull fma2(ull a, ull b, ull c) {
    ull d; asm("fma.rn.f32x2 %0, %1, %2, %3;" : "=l"(d) : "l"(a), "l"(b), "l"(c));
    return d;
}
__device__ __forceinline__ float2 unpack2(ull v) {
    float2 r; asm("mov.b64 {%0,%1}, %2;" : "=f"(r.x), "=f"(r.y) : "l"(v)); return r;
}

// ---------------------------------------------------------------------------
// Init: ego0 (fp32 + fp16 shadow) and layer-0 columns of out. Thread per pair.
// ---------------------------------------------------------------------------
__global__ void init_kernel(const float* __restrict__ ue,
                            const float* __restrict__ ie,
                            float* __restrict__ out) {
    int idx = blockIdx.x * blockDim.x + threadIdx.x;  // pair index
    if (idx >= NTOT * 32) return;
    int node = idx >> 5;
    int dp = idx & 31;
    const float2* src = (node < N_USERS_C)
        ? (const float2*)ue + idx
        : (const float2*)ie + (idx - N_USERS_C * 32);
    float2 v = __ldg(src);
    *(float2*)&g_ego[0][(size_t)node * 64 + dp * 2] = v;
    g_egoh[0][(size_t)node * 32 + dp] = __floats2half2_rn(v.x, v.y);
    *(float2*)&out[(size_t)node * 256 + dp * 2] = v;
}

__global__ void zero_cnt_kernel() {
    int i = blockIdx.x * blockDim.x + threadIdx.x;
    if (i < NSEG) g_cnt[i] = 0;
}

__global__ void hist_kernel(const int* __restrict__ rows,
                            const int* __restrict__ cols) {
    int e = blockIdx.x * blockDim.x + threadIdx.x;
    if (e >= NNZ_E) return;
    int r = __ldg(rows + e);
    int c = __ldg(cols + e);
    int t = (c >= TSPLIT);
    atomicAdd(&g_cnt[r * NTILES + t], 1);
}

// Per-block exclusive scan of 4096 counts (1024 thr x 4); block total to g_bsum.
__global__ void scan_local_kernel() {
    __shared__ int wsum[32];
    int b = blockIdx.x, t = threadIdx.x;
    int base = b * 4096 + t * 4;
    int v0 = 0, v1 = 0, v2 = 0, v3 = 0;
    if (base + 0 < NSEG) v0 = g_cnt[base + 0];
    if (base + 1 < NSEG) v1 = g_cnt[base + 1];
    if (base + 2 < NSEG) v2 = g_cnt[base + 2];
    if (base + 3 < NSEG) v3 = g_cnt[base + 3];
    int tsum = v0 + v1 + v2 + v3;
    int lane = t & 31, w = t >> 5;
    int x = tsum;
#pragma unroll
    for (int d = 1; d < 32; d <<= 1) {
        int y = __shfl_up_sync(0xffffffffu, x, d);
        if (lane >= d) x += y;
    }
    if (lane == 31) wsum[w] = x;
    __syncthreads();
    if (t < 32) {
        int y = wsum[t];
#pragma unroll
        for (int d = 1; d < 32; d <<= 1) {
            int z = __shfl_up_sync(0xffffffffu, y, d);
            if (t >= d) y += z;
        }
        wsum[t] = y;
    }
    __syncthreads();
    int woff = (w == 0) ? 0 : wsum[w - 1];
    int ex = woff + x - tsum;
    if (base + 0 < NSEG) g_scan[base + 0] = ex;
    ex += v0;
    if (base + 1 < NSEG) g_scan[base + 1] = ex;
    ex += v1;
    if (base + 2 < NSEG) g_scan[base + 2] = ex;
    ex += v2;
    if (base + 3 < NSEG) g_scan[base + 3] = ex;
    if (t == 0) g_bsum[b] = wsum[31];
}

// Exclusive scan of the NB2 block sums (single block of 256).
__global__ void scan_block_kernel() {
    __shared__ int wsum[8];
    int t = threadIdx.x;
    int v = (t < NB2) ? g_bsum[t] : 0;
    int lane = t & 31, w = t >> 5;
    int x = v;
#pragma unroll
    for (int d = 1; d < 32; d <<= 1) {
        int y = __shfl_up_sync(0xffffffffu, x, d);
        if (lane >= d) x += y;
    }
    if (lane == 31) wsum[w] = x;
    __syncthreads();
    if (t < 8) {
        int y = wsum[t];
#pragma unroll
        for (int d = 1; d < 8; d <<= 1) {
            int z = __shfl_up_sync(0xffu, y, d, 8);
            if (t >= d) y += z;
        }
        wsum[t] = y;
    }
    __syncthreads();
    int woff = (w == 0) ? 0 : wsum[w - 1];
    if (t < NB2) g_boff[t] = woff + x - v;
}

__global__ void scan_finish_kernel() {
    int i = blockIdx.x * blockDim.x + threadIdx.x;
    if (i < NSEG) {
        int r = g_scan[i] + g_boff[i >> 12];
        g_rp2[i] = r;
        g_cur[i] = r;
    }
    if (i == 0) g_rp2[NSEG] = NNZ_E;
}

__global__ void scatter_kernel(const int* __restrict__ rows,
                               const int* __restrict__ cols,
                               const float* __restrict__ vals) {
    int e = blockIdx.x * blockDim.x + threadIdx.x;
    if (e >= NNZ_E) return;
    int r = __ldg(rows + e);
    int c = __ldg(cols + e);
    float v = __ldg(vals + e);
    int t = (c >= TSPLIT);
    int pos = atomicAdd(&g_cur[r * NTILES + t], 1);
    __stcs(g_csv + pos, make_int2(c, __float_as_int(v)));
}

// ---------------------------------------------------------------------------
// SpMM pass over column tile 0 (cols < TSPLIT): half-warp per row, exclusive
// ownership, fp16 gather (1 L2 line/row) / fp32 accumulate, streaming stores.
// ---------------------------------------------------------------------------
__global__ void __launch_bounds__(256)
spmm_pass_kernel(int pp) {
    int gtid = blockIdx.x * blockDim.x + threadIdx.x;
    int r = gtid >> 4;
    if (r >= NTOT) return;
    int j = threadIdx.x & 15;
    unsigned hmask = 0xFFFFu << (threadIdx.x & 16);
    ull pol = mk_evict_last();

    const uint2* xh = (const uint2*)g_egoh[pp];   // 16 uint2 per row
    float4* side4 = (float4*)g_side;

    int s = __ldg(g_rp2 + r * NTILES);
    int e = __ldg(g_rp2 + r * NTILES + 1);

    float4 acc = make_float4(0.f, 0.f, 0.f, 0.f);
    for (int p = s; p < e; p += 16) {
        int idx = p + j;
        int cj = -1; float vj = 0.f;
        if (idx < e) {
            int2 cv = __ldcs(g_csv + idx);
            cj = cv.x; vj = __int_as_float(cv.y);
        }
#pragma unroll
        for (int q = 0; q < 16; q++) {
            int cc   = __shfl_sync(hmask, cj, q, 16);
            float vv = __shfl_sync(hmask, vj, q, 16);
            if (cc >= 0) {
                uint2 u = ldg_h(xh + (size_t)cc * 16 + j, pol);
                float2 fa = __half22float2(*(__half2*)&u.x);
                float2 fb = __half22float2(*(__half2*)&u.y);
                acc.x += vv * fa.x;
                acc.y += vv * fa.y;
                acc.z += vv * fb.x;
                acc.w += vv * fb.y;
            }
        }
    }
    __stcs(side4 + (size_t)r * 16 + j, acc);
}

// ---------------------------------------------------------------------------
// Fused: tile-1 SpMM (fp16 gather, seeded with g_side partial) -> smem tiles ->
// GC/Bi GEMM (FFMA2) + lrelu + row-L2-normalize -> out + ego_next (+fp16 shadow).
// 512 threads/block, 2 blocks/SM; PERSISTENT grid (296 blocks): weights loaded
// and transposed ONCE per block, amortized over ~21 chunks.
// ---------------------------------------------------------------------------
__global__ void __launch_bounds__(512, 2)
fused_layer_kernel(const float* __restrict__ gw,
                   const float* __restrict__ gb,
                   const float* __restrict__ bw,
                   const float* __restrict__ bb,
                   float* __restrict__ out,
                   int col_off, int pp) {
    extern __shared__ float sh[];
    float* s_wgc  = sh;                 // 4096: wT[k*64+d]
    float* s_wbi  = sh + 4096;          // 4096
    float* s_side = sh + 8192;          // 64*68
    float* s_prod = sh + 8192 + 4352;   // 64*68 (reused as e-buffer)

    const float*  ego = g_ego[pp];
    float*   ego_next = g_ego[pp ^ 1];
    const float4* x4  = (const float4*)ego;
    const uint2*  xh  = (const uint2*)g_egoh[pp];
    __half2* egoh_next = g_egoh[pp ^ 1];
    const float4* side4 = (const float4*)g_side;

    int t = threadIdx.x;
    int j = t & 15;
    int h = t >> 4;                       // half-warp id 0..31
    unsigned hmask = 0xFFFFu << (t & 16);
    ull pol = mk_evict_last();

    // Weights: loaded once per persistent block
    for (int idx = t; idx < 4096; idx += 512) {
        int d = idx & 63, k = idx >> 6;
        s_wgc[k * 64 + d] = gw[d * 64 + k];
        s_wbi[k * 64 + d] = bw[d * 64 + k];
    }

    const int d0 = (t & 15) * 4;
    const int n0 = (t >> 4) * 2;          // 2 nodes per thread
    ull bg2[2], bb2[2];
#pragma unroll
    for (int p = 0; p < 2; p++) {
        bg2[p] = pack2(__ldg(gb + d0 + 2 * p), __ldg(gb + d0 + 2 * p + 1));
        bb2[p] = pack2(__ldg(bb + d0 + 2 * p), __ldg(bb + d0 + 2 * p + 1));
    }

    for (int c = blockIdx.x; c < CHUNKS; c += gridDim.x) {
        __syncthreads();
        int base = c * 64;

        // ---- Phase 1: tile-1 SpMM seeded with side partial (2 rows/half-warp) ----
#pragma unroll
        for (int i = 0; i < 2; i++) {
            int r = base + h * 2 + i;
            int s = __ldg(g_rp2 + r * NTILES + 1);
            int e = __ldg(g_rp2 + r * NTILES + 2);
            float4 acc = __ldcs(side4 + (size_t)r * 16 + j);
            for (int p = s; p < e; p += 16) {
                int idx = p + j;
                int cj = -1; float vj = 0.f;
                if (idx < e) {
                    int2 cv = __ldcs(g_csv + idx);
                    cj = cv.x; vj = __int_as_float(cv.y);
                }
#pragma unroll
                for (int q = 0; q < 16; q++) {
                    int cc   = __shfl_sync(hmask, cj, q, 16);
                    float vv = __shfl_sync(hmask, vj, q, 16);
                    if (cc >= 0) {
                        uint2 u = ldg_h(xh + (size_t)cc * 16 + j, pol);
                        float2 fa = __half22float2(*(__half2*)&u.x);
                        float2 fb = __half22float2(*(__half2*)&u.y);
                        acc.x += vv * fa.x;
                        acc.y += vv * fa.y;
                        acc.z += vv * fb.x;
                        acc.w += vv * fb.y;
                    }
                }
            }
            float4 ev = __ldg(x4 + (size_t)r * 16 + j);   // fp32 ego for Bi branch
            int node = h * 2 + i;
            *(float4*)&s_side[node * 68 + j * 4] = acc;
            *(float4*)&s_prod[node * 68 + j * 4] =
                make_float4(acc.x * ev.x, acc.y * ev.y, acc.z * ev.z, acc.w * ev.w);
        }
        __syncthreads();

        // ---- Phase 2: dense GC/Bi GEMM via packed f32x2 (2 nodes x 4 dims) ----
        ull accg2[2][2], accb2[2][2];
#pragma unroll
        for (int i = 0; i < 2; i++)
#pragma unroll
            for (int p = 0; p < 2; p++) {
                accg2[i][p] = bg2[p];
                accb2[i][p] = bb2[p];
            }

#pragma unroll 8
        for (int k = 0; k < 64; k++) {
            const ull* wgp = (const ull*)&s_wgc[k * 64 + d0];
            const ull* wbp = (const ull*)&s_wbi[k * 64 + d0];
            ull wg0 = wgp[0], wg1 = wgp[1];
            ull wb0 = wbp[0], wb1 = wbp[1];
#pragma unroll
            for (int i = 0; i < 2; i++) {
                float sv = s_side[(n0 + i) * 68 + k];
                float pv = s_prod[(n0 + i) * 68 + k];
                ull sv2 = pack2(sv, sv);
                ull pv2 = pack2(pv, pv);
                accg2[i][0] = fma2(sv2, wg0, accg2[i][0]);
                accg2[i][1] = fma2(sv2, wg1, accg2[i][1]);
                accb2[i][0] = fma2(pv2, wb0, accb2[i][0]);
                accb2[i][1] = fma2(pv2, wb1, accb2[i][1]);
            }
        }
        __syncthreads();

        // e = lrelu(gc) + lrelu(bi) into smem (reuse s_prod)
#pragma unroll
        for (int i = 0; i < 2; i++)
#pragma unroll
            for (int p = 0; p < 2; p++) {
                float2 a = unpack2(accg2[i][p]);
                float2 b = unpack2(accb2[i][p]);
                float e0 = fmaxf(a.x, 0.01f * a.x) + fmaxf(b.x, 0.01f * b.x);
                float e1 = fmaxf(a.y, 0.01f * a.y) + fmaxf(b.y, 0.01f * b.y);
                s_prod[(n0 + i) * 68 + d0 + 2 * p]     = e0;
                s_prod[(n0 + i) * 68 + d0 + 2 * p + 1] = e1;
            }
        __syncthreads();

        // Row norms + global writes: 8 threads/row (node = t/8, oct = t%8)
        int node = t >> 3, oc = t & 7;
        float ss = 0.f;
#pragma unroll
        for (int m = 0; m < 8; m++) {
            float v = s_prod[node * 68 + oc * 8 + m];
            ss += v * v;
        }
        ss += __shfl_xor_sync(0xffffffffu, ss, 1);
        ss += __shfl_xor_sync(0xffffffffu, ss, 2);
        ss += __shfl_xor_sync(0xffffffffu, ss, 4);
        float inv = 1.f / fmaxf(sqrtf(ss), 1e-12f);

        size_t gnode = (size_t)(base + node);
        unsigned hb[4];
#pragma unroll
        for (int m = 0; m < 8; m += 4) {
            float4 v = *(const float4*)&s_prod[node * 68 + oc * 8 + m];
            *(float4*)&ego_next[gnode * 64 + oc * 8 + m] = v;
            __half2 h0 = __floats2half2_rn(v.x, v.y);
            __half2 h1 = __floats2half2_rn(v.z, v.w);
            hb[m / 2]     = *(unsigned*)&h0;
            hb[m / 2 + 1] = *(unsigned*)&h1;
            float4 vn = make_float4(v.x * inv, v.y * inv, v.z * inv, v.w * inv);
            __stcs((float4*)&out[gnode * 256 + col_off + oc * 8 + m], vn);
        }
        // fp16 shadow for next layer's gathers (one 16B store: 8 dims)
        *(uint4*)&egoh_next[gnode * 32 + oc * 4] = make_uint4(hb[0], hb[1], hb[2], hb[3]);
    }
}

// ---------------------------------------------------------------------------
extern "C" void kernel_launch(void* const* d_in, const int* in_sizes, int n_in,
                              void* d_out, int out_size) {
    const int*   rows = (const int*)d_in[0];
    const int*   cols = (const int*)d_in[1];
    const float* vals = (const float*)d_in[2];
    const float* ue   = (const float*)d_in[3];
    const float* ie   = (const float*)d_in[4];
    const float* gw   = (const float*)d_in[5];
    const float* gb   = (const float*)d_in[6];
    const float* bw   = (const float*)d_in[7];
    const float* bb   = (const float*)d_in[8];
    float* out = (float*)d_out;

    const int smem_bytes = (4096 * 2 + 4352 * 2) * 4;  // 67584 B
    cudaFuncSetAttribute(fused_layer_kernel,
                         cudaFuncAttributeMaxDynamicSharedMemorySize, smem_bytes);

    init_kernel<<<(NTOT * 32 + 255) / 256, 256>>>(ue, ie, out);

    // ---- (row, col-tile)-sorted edge list build (once; reused by all layers) ----
    zero_cnt_kernel<<<(NSEG + 255) / 256, 256>>>();
    hist_kernel<<<(NNZ_E + 255) / 256, 256>>>(rows, cols);
    scan_local_kernel<<<NB2, 1024>>>();
    scan_block_kernel<<<1, 256>>>();
    scan_finish_kernel<<<(NSEG + 255) / 256, 256>>>();
    scatter_kernel<<<(NNZ_E + 255) / 256, 256>>>(rows, cols, vals);

    // ---- 3 layers: tile-0 pass + fused(tile-1 + dense, persistent grid) ----
    const int pass_blocks = (NTOT * 16 + 255) / 256;  // one half-warp per row
    for (int i = 0; i < NLAYERS; i++) {
        int pp = i & 1;
        spmm_pass_kernel<<<pass_blocks, 256>>>(pp);
        fused_layer_kernel<<<FUSED_GRID, 512, smem_bytes>>>(
            gw + i * 4096, gb + i * 64, bw + i * 4096, bb + i * 64,
            out, (i + 1) * 64, pp);
    }
}

// round 17
// speedup vs baseline: 1.4144x; 1.0544x over previous
#include <cuda_runtime.h>
#include <cuda_fp16.h>

#define N_USERS_C 200000
#define NTOT      400000
#define DIM       64
#define NNZ_E     12800000
#define NLAYERS   3
#define CHUNKS    (NTOT / 64)
#define FUSED_GRID 296   // 2 blocks/SM x 148 SM; persistent

#define NB2       ((NTOT + 4095) / 4096)     // 98

typedef unsigned long long ull;

// ---- device-global scratch (allocation-free rule) ----
__device__ float   g_ego[2][(size_t)NTOT * DIM];   // fp32 ego (ping-pong)
__device__ __half2 g_egoh[2][(size_t)NTOT * 32];   // fp16 shadow (gather source)
__device__ int   g_cnt[NTOT];
__device__ int   g_scan[NTOT];
__device__ int   g_rp[NTOT + 1];
__device__ int   g_cur[NTOT];
__device__ int   g_bsum[NB2];
__device__ int   g_boff[NB2];
__device__ int2  g_csv[NNZ_E];               // (col, float-bits of val)

// L2 evict-last policy + hinted 64-bit fp16 gather
__device__ __forceinline__ ull mk_evict_last() {
    ull pol;
    asm("createpolicy.fractional.L2::evict_last.b64 %0, 1.0;" : "=l"(pol));
    return pol;
}
__device__ __forceinline__ uint2 ldg_h(const uint2* p, ull pol) {
    uint2 r;
    asm volatile("ld.global.nc.L2::cache_hint.v2.u32 {%0,%1}, [%2], %3;"
                 : "=r"(r.x), "=r"(r.y) : "l"(p), "l"(pol));
    return r;
}

// Packed f32x2 helpers (FFMA2 — only reachable via PTX on sm_103a)
__device__ __forceinline__ ull pack2(float lo, float hi) {
    ull r; asm("mov.b64 %0, {%1,%2};" : "=l"(r) : "f"(lo), "f"(hi)); return r;
}
__device__ __forceinline__ ull fma2(ull a, ull b, ull c) {
    ull d; asm("fma.rn.f32x2 %0, %1, %2, %3;" : "=l"(d) : "l"(a), "l"(b), "l"(c));
    return d;
}
__device__ __forceinline__ float2 unpack2(ull v) {
    float2 r; asm("mov.b64 {%0,%1}, %2;" : "=f"(r.x), "=f"(r.y) : "l"(v)); return r;
}

// ---------------------------------------------------------------------------
// Init: ego0 (fp32 + fp16 shadow) and layer-0 columns of out. Thread per pair.
// ---------------------------------------------------------------------------
__global__ void init_kernel(const float* __restrict__ ue,
                            const float* __restrict__ ie,
                            float* __restrict__ out) {
    int idx = blockIdx.x * blockDim.x + threadIdx.x;  // pair index
    if (idx >= NTOT * 32) return;
    int node = idx >> 5;
    int dp = idx & 31;
    const float2* src = (node < N_USERS_C)
        ? (const float2*)ue + idx
        : (const float2*)ie + (idx - N_USERS_C * 32);
    float2 v = __ldg(src);
    *(float2*)&g_ego[0][(size_t)node * 64 + dp * 2] = v;
    g_egoh[0][(size_t)node * 32 + dp] = __floats2half2_rn(v.x, v.y);
    *(float2*)&out[(size_t)node * 256 + dp * 2] = v;
}

__global__ void zero_cnt_kernel() {
    int i = blockIdx.x * blockDim.x + threadIdx.x;
    if (i < NTOT) g_cnt[i] = 0;
}

__global__ void hist_kernel(const int* __restrict__ rows) {
    int e = blockIdx.x * blockDim.x + threadIdx.x;
    if (e < NNZ_E) atomicAdd(&g_cnt[__ldg(rows + e)], 1);
}

// Per-block exclusive scan of 4096 counts (1024 thr x 4); block total to g_bsum.
__global__ void scan_local_kernel() {
    __shared__ int wsum[32];
    int b = blockIdx.x, t = threadIdx.x;
    int base = b * 4096 + t * 4;
    int v0 = 0, v1 = 0, v2 = 0, v3 = 0;
    if (base + 0 < NTOT) v0 = g_cnt[base + 0];
    if (base + 1 < NTOT) v1 = g_cnt[base + 1];
    if (base + 2 < NTOT) v2 = g_cnt[base + 2];
    if (base + 3 < NTOT) v3 = g_cnt[base + 3];
    int tsum = v0 + v1 + v2 + v3;
    int lane = t & 31, w = t >> 5;
    int x = tsum;
#pragma unroll
    for (int d = 1; d < 32; d <<= 1) {
        int y = __shfl_up_sync(0xffffffffu, x, d);
        if (lane >= d) x += y;
    }
    if (lane == 31) wsum[w] = x;
    __syncthreads();
    if (t < 32) {
        int y = wsum[t];
#pragma unroll
        for (int d = 1; d < 32; d <<= 1) {
            int z = __shfl_up_sync(0xffffffffu, y, d);
            if (t >= d) y += z;
        }
        wsum[t] = y;
    }
    __syncthreads();
    int woff = (w == 0) ? 0 : wsum[w - 1];
    int ex = woff + x - tsum;
    if (base + 0 < NTOT) g_scan[base + 0] = ex;
    ex += v0;
    if (base + 1 < NTOT) g_scan[base + 1] = ex;
    ex += v1;
    if (base + 2 < NTOT) g_scan[base + 2] = ex;
    ex += v2;
    if (base + 3 < NTOT) g_scan[base + 3] = ex;
    if (t == 0) g_bsum[b] = wsum[31];
}

// Exclusive scan of the NB2 (=98) block sums (single block of 128).
__global__ void scan_block_kernel() {
    __shared__ int wsum[4];
    int t = threadIdx.x;
    int v = (t < NB2) ? g_bsum[t] : 0;
    int lane = t & 31, w = t >> 5;
    int x = v;
#pragma unroll
    for (int d = 1; d < 32; d <<= 1) {
        int y = __shfl_up_sync(0xffffffffu, x, d);
        if (lane >= d) x += y;
    }
    if (lane == 31) wsum[w] = x;
    __syncthreads();
    if (t < 4) {
        int y = wsum[t];
#pragma unroll
        for (int d = 1; d < 4; d <<= 1) {
            int z = __shfl_up_sync(0xFu, y, d, 4);
            if (t >= d) y += z;
        }
        wsum[t] = y;
    }
    __syncthreads();
    int woff = (w == 0) ? 0 : wsum[w - 1];
    if (t < NB2) g_boff[t] = woff + x - v;
}

__global__ void scan_finish_kernel() {
    int i = blockIdx.x * blockDim.x + threadIdx.x;
    if (i < NTOT) {
        int r = g_scan[i] + g_boff[i >> 12];
        g_rp[i] = r;
        g_cur[i] = r;
    }
    if (i == 0) g_rp[NTOT] = NNZ_E;
}

__global__ void scatter_kernel(const int* __restrict__ rows,
                               const int* __restrict__ cols,
                               const float* __restrict__ vals) {
    int e = blockIdx.x * blockDim.x + threadIdx.x;
    if (e >= NNZ_E) return;
    int r = __ldg(rows + e);
    int c = __ldg(cols + e);
    float v = __ldg(vals + e);
    int pos = atomicAdd(&g_cur[r], 1);
    __stcs(g_csv + pos, make_int2(c, __float_as_int(v)));
}

// ---------------------------------------------------------------------------
// Single fused layer kernel (persistent, tile-less): full-row CSR SpMM
// (fp16 gather — whole 51MB shadow is L2-resident — fp32 accumulate) ->
// smem tiles -> GC/Bi GEMM (FFMA2) + lrelu + row-L2-normalize ->
// out + fp32 ego_next + fp16 shadow.
// 512 threads/block, 2 blocks/SM, 296 blocks; weights loaded once per block.
// ---------------------------------------------------------------------------
__global__ void __launch_bounds__(512, 2)
fused_layer_kernel(const float* __restrict__ gw,
                   const float* __restrict__ gb,
                   const float* __restrict__ bw,
                   const float* __restrict__ bb,
                   float* __restrict__ out,
                   int col_off, int pp) {
    extern __shared__ float sh[];
    float* s_wgc  = sh;                 // 4096: wT[k*64+d]
    float* s_wbi  = sh + 4096;          // 4096
    float* s_side = sh + 8192;          // 64*68
    float* s_prod = sh + 8192 + 4352;   // 64*68 (reused as e-buffer)

    const float*  ego = g_ego[pp];
    float*   ego_next = g_ego[pp ^ 1];
    const float4* x4  = (const float4*)ego;
    const uint2*  xh  = (const uint2*)g_egoh[pp];
    __half2* egoh_next = g_egoh[pp ^ 1];

    int t = threadIdx.x;
    int j = t & 15;
    int h = t >> 4;                       // half-warp id 0..31
    unsigned hmask = 0xFFFFu << (t & 16);
    ull pol = mk_evict_last();

    // Weights: loaded once per persistent block
    for (int idx = t; idx < 4096; idx += 512) {
        int d = idx & 63, k = idx >> 6;
        s_wgc[k * 64 + d] = gw[d * 64 + k];
        s_wbi[k * 64 + d] = bw[d * 64 + k];
    }

    const int d0 = (t & 15) * 4;
    const int n0 = (t >> 4) * 2;          // 2 nodes per thread
    ull bg2[2], bb2[2];
#pragma unroll
    for (int p = 0; p < 2; p++) {
        bg2[p] = pack2(__ldg(gb + d0 + 2 * p), __ldg(gb + d0 + 2 * p + 1));
        bb2[p] = pack2(__ldg(bb + d0 + 2 * p), __ldg(bb + d0 + 2 * p + 1));
    }

    for (int c = blockIdx.x; c < CHUNKS; c += gridDim.x) {
        __syncthreads();
        int base = c * 64;

        // ---- Phase 1: full-row SpMM (2 rows/half-warp), fp16 gather ----
#pragma unroll
        for (int i = 0; i < 2; i++) {
            int r = base + h * 2 + i;
            int s = __ldg(g_rp + r), e = __ldg(g_rp + r + 1);
            float4 acc = make_float4(0.f, 0.f, 0.f, 0.f);
            for (int p = s; p < e; p += 16) {
                int idx = p + j;
                int cj = -1; float vj = 0.f;
                if (idx < e) {
                    int2 cv = __ldcs(g_csv + idx);
                    cj = cv.x; vj = __int_as_float(cv.y);
                }
#pragma unroll
                for (int q = 0; q < 16; q++) {
                    int cc   = __shfl_sync(hmask, cj, q, 16);
                    float vv = __shfl_sync(hmask, vj, q, 16);
                    if (cc >= 0) {
                        uint2 u = ldg_h(xh + (size_t)cc * 16 + j, pol);
                        float2 fa = __half22float2(*(__half2*)&u.x);
                        float2 fb = __half22float2(*(__half2*)&u.y);
                        acc.x += vv * fa.x;
                        acc.y += vv * fa.y;
                        acc.z += vv * fb.x;
                        acc.w += vv * fb.y;
                    }
                }
            }
            float4 ev = __ldg(x4 + (size_t)r * 16 + j);   // fp32 ego for Bi branch
            int node = h * 2 + i;
            *(float4*)&s_side[node * 68 + j * 4] = acc;
            *(float4*)&s_prod[node * 68 + j * 4] =
                make_float4(acc.x * ev.x, acc.y * ev.y, acc.z * ev.z, acc.w * ev.w);
        }
        __syncthreads();

        // ---- Phase 2: dense GC/Bi GEMM via packed f32x2 (2 nodes x 4 dims) ----
        ull accg2[2][2], accb2[2][2];
#pragma unroll
        for (int i = 0; i < 2; i++)
#pragma unroll
            for (int p = 0; p < 2; p++) {
                accg2[i][p] = bg2[p];
                accb2[i][p] = bb2[p];
            }

#pragma unroll 8
        for (int k = 0; k < 64; k++) {
            const ull* wgp = (const ull*)&s_wgc[k * 64 + d0];
            const ull* wbp = (const ull*)&s_wbi[k * 64 + d0];
            ull wg0 = wgp[0], wg1 = wgp[1];
            ull wb0 = wbp[0], wb1 = wbp[1];
#pragma unroll
            for (int i = 0; i < 2; i++) {
                float sv = s_side[(n0 + i) * 68 + k];
                float pv = s_prod[(n0 + i) * 68 + k];
                ull sv2 = pack2(sv, sv);
                ull pv2 = pack2(pv, pv);
                accg2[i][0] = fma2(sv2, wg0, accg2[i][0]);
                accg2[i][1] = fma2(sv2, wg1, accg2[i][1]);
                accb2[i][0] = fma2(pv2, wb0, accb2[i][0]);
                accb2[i][1] = fma2(pv2, wb1, accb2[i][1]);
            }
        }
        __syncthreads();

        // e = lrelu(gc) + lrelu(bi) into smem (reuse s_prod)
#pragma unroll
        for (int i = 0; i < 2; i++)
#pragma unroll
            for (int p = 0; p < 2; p++) {
                float2 a = unpack2(accg2[i][p]);
                float2 b = unpack2(accb2[i][p]);
                float e0 = fmaxf(a.x, 0.01f * a.x) + fmaxf(b.x, 0.01f * b.x);
                float e1 = fmaxf(a.y, 0.01f * a.y) + fmaxf(b.y, 0.01f * b.y);
                s_prod[(n0 + i) * 68 + d0 + 2 * p]     = e0;
                s_prod[(n0 + i) * 68 + d0 + 2 * p + 1] = e1;
            }
        __syncthreads();

        // Row norms + global writes: 8 threads/row (node = t/8, oct = t%8)
        int node = t >> 3, oc = t & 7;
        float ss = 0.f;
#pragma unroll
        for (int m = 0; m < 8; m++) {
            float v = s_prod[node * 68 + oc * 8 + m];
            ss += v * v;
        }
        ss += __shfl_xor_sync(0xffffffffu, ss, 1);
        ss += __shfl_xor_sync(0xffffffffu, ss, 2);
        ss += __shfl_xor_sync(0xffffffffu, ss, 4);
        float inv = 1.f / fmaxf(sqrtf(ss), 1e-12f);

        size_t gnode = (size_t)(base + node);
        unsigned hb[4];
#pragma unroll
        for (int m = 0; m < 8; m += 4) {
            float4 v = *(const float4*)&s_prod[node * 68 + oc * 8 + m];
            *(float4*)&ego_next[gnode * 64 + oc * 8 + m] = v;
            __half2 h0 = __floats2half2_rn(v.x, v.y);
            __half2 h1 = __floats2half2_rn(v.z, v.w);
            hb[m / 2]     = *(unsigned*)&h0;
            hb[m / 2 + 1] = *(unsigned*)&h1;
            float4 vn = make_float4(v.x * inv, v.y * inv, v.z * inv, v.w * inv);
            __stcs((float4*)&out[gnode * 256 + col_off + oc * 8 + m], vn);
        }
        // fp16 shadow for next layer's gathers (one 16B store: 8 dims)
        *(uint4*)&egoh_next[gnode * 32 + oc * 4] = make_uint4(hb[0], hb[1], hb[2], hb[3]);
    }
}

// ---------------------------------------------------------------------------
extern "C" void kernel_launch(void* const* d_in, const int* in_sizes, int n_in,
                              void* d_out, int out_size) {
    const int*   rows = (const int*)d_in[0];
    const int*   cols = (const int*)d_in[1];
    const float* vals = (const float*)d_in[2];
    const float* ue   = (const float*)d_in[3];
    const float* ie   = (const float*)d_in[4];
    const float* gw   = (const float*)d_in[5];
    const float* gb   = (const float*)d_in[6];
    const float* bw   = (const float*)d_in[7];
    const float* bb   = (const float*)d_in[8];
    float* out = (float*)d_out;

    const int smem_bytes = (4096 * 2 + 4352 * 2) * 4;  // 67584 B
    cudaFuncSetAttribute(fused_layer_kernel,
                         cudaFuncAttributeMaxDynamicSharedMemorySize, smem_bytes);

    init_kernel<<<(NTOT * 32 + 255) / 256, 256>>>(ue, ie, out);

    // ---- CSR build (once; reused by all 3 layers) ----
    zero_cnt_kernel<<<(NTOT + 255) / 256, 256>>>();
    hist_kernel<<<(NNZ_E + 255) / 256, 256>>>(rows);
    scan_local_kernel<<<NB2, 1024>>>();
    scan_block_kernel<<<1, 128>>>();
    scan_finish_kernel<<<(NTOT + 255) / 256, 256>>>();
    scatter_kernel<<<(NNZ_E + 255) / 256, 256>>>(rows, cols, vals);

    // ---- 3 layers: ONE persistent fused kernel each ----
    for (int i = 0; i < NLAYERS; i++) {
        int pp = i & 1;
        fused_layer_kernel<<<FUSED_GRID, 512, smem_bytes>>>(
            gw + i * 4096, gb + i * 64, bw + i * 4096, bb + i * 64,
            out, (i + 1) * 64, pp);
    }
}